// round 5
// baseline (speedup 1.0000x reference)
#include <cuda_runtime.h>
#include <cstdint>

// ---------------------------------------------------------------------------
// SparseResBlock on sm_103a — tf32 mma.sync, 128-row CTA tiles.
//   h   = ReLU(BN1(spconv(x, W1, nbr1)))
//   h2  = BN2(spconv(h, W2, nbr2))
//   out = ReLU(h2 + BNd(x @ Wd))
// N=200000, Cin=64, Cout=128, K=27.
// ---------------------------------------------------------------------------

#define EPS_BN 1e-5f

constexpr int COUT   = 128;
constexpr int ROWS   = 128;       // output rows per CTA
constexpr int NTH    = 512;       // 16 warps: 8 row-warps x 2 col-warps
constexpr int MAXN   = 200000;
constexpr int MAXBLK = (MAXN + ROWS - 1) / ROWS;   // 1563

// ---- device-global scratch (no allocation allowed in kernel_launch) ----
__device__ float g_h1 [(size_t)MAXN * COUT];  // conv1 raw fp32
__device__ float g_h1t[(size_t)MAXN * COUT];  // relu(BN1(h1)) fp32
__device__ float g_h2 [(size_t)MAXN * COUT];  // conv2 raw fp32
__device__ float g_sk [(size_t)MAXN * COUT];  // skip raw fp32
__device__ float g_wp1[27 * 64  * 128];       // W1 in mma-fragment order
__device__ float g_wp2[27 * 128 * 128];       // W2 in mma-fragment order
__device__ float g_wpd[64 * 128];             // Wd in mma-fragment order
__device__ float g_part1[(size_t)MAXBLK * 256];
__device__ float g_part2[(size_t)MAXBLK * 256];
__device__ float g_partd[(size_t)MAXBLK * 256];
__device__ float g_sc1[COUT], g_sh1[COUT];
__device__ float g_sc2[COUT], g_sh2[COUT];
__device__ float g_scd[COUT], g_shd[COUT];

// ---------------------------------------------------------------------------
__device__ __forceinline__ uint32_t tf32u(float x) {
    uint32_t u;
    asm("cvt.rna.tf32.f32 %0, %1;" : "=r"(u) : "f"(x));
    return u;
}
__device__ __forceinline__ float tf32r(float x) {
    return __uint_as_float(tf32u(x));
}

__device__ __forceinline__ void cp16(uint32_t dst, const void* src, int sz) {
    // cp.async 16B with runtime src-size (0 => zero-fill)
    asm volatile("cp.async.cg.shared.global [%0], [%1], 16, %2;\n"
                 :: "r"(dst), "l"(src), "r"(sz));
}
__device__ __forceinline__ void cp_commit() {
    asm volatile("cp.async.commit_group;\n" ::: "memory");
}
__device__ __forceinline__ void cp_wait_all() {
    asm volatile("cp.async.wait_group 0;\n" ::: "memory");
}

__device__ __forceinline__ void mma_tf32(float acc[4],
                                         uint32_t a0, uint32_t a1,
                                         uint32_t a2, uint32_t a3,
                                         uint32_t b0, uint32_t b1) {
    asm volatile(
        "mma.sync.aligned.m16n8k8.row.col.f32.tf32.tf32.f32 "
        "{%0,%1,%2,%3}, {%4,%5,%6,%7}, {%8,%9}, {%0,%1,%2,%3};\n"
        : "+f"(acc[0]), "+f"(acc[1]), "+f"(acc[2]), "+f"(acc[3])
        : "r"(a0), "r"(a1), "r"(a2), "r"(a3), "r"(b0), "r"(b1));
}

// ---------------------------------------------------------------------------
// Weight reorder: W[K][CIN][128] -> m16n8k8 .row.col fragment order:
//   frag gid = ((k*KC + kc)*16 + nt)*32 + lane holds float2
//     {W[k][kc*8 + lane%4    ][nt*8 + lane/4],
//      W[k][kc*8 + lane%4 + 4][nt*8 + lane/4]}   (tf32-rounded)
// so a warp's B-frag load is one coalesced 256B LDG.64.
// ---------------------------------------------------------------------------
__global__ void prep_w(const float* __restrict__ W, float* __restrict__ Wp,
                       int K, int CIN)
{
    const int KC    = CIN / 8;
    const int total = K * KC * 16 * 32;
    const int gid   = blockIdx.x * blockDim.x + threadIdx.x;
    if (gid >= total) return;
    const int lane = gid & 31;
    int t  = gid >> 5;
    const int nt = t & 15;  t >>= 4;
    const int kc = t % KC;
    const int k  = t / KC;
    const int row = kc * 8 + (lane & 3);
    const int col = nt * 8 + (lane >> 2);
    const size_t base = ((size_t)k * CIN + row) * COUT + col;
    Wp[(size_t)gid * 2]     = tf32r(W[base]);
    Wp[(size_t)gid * 2 + 1] = tf32r(W[base + 4 * COUT]);
}

// elementwise: y = relu(x*sc + sh), per-channel sc/sh (COUT=128)
__global__ void bn_relu(const float* __restrict__ x,
                        const float* __restrict__ sc,
                        const float* __restrict__ sh,
                        float* __restrict__ y, int total4)
{
    const int i = blockIdx.x * blockDim.x + threadIdx.x;
    if (i >= total4) return;
    const int c4 = i & 31;
    float4 v = reinterpret_cast<const float4*>(x)[i];
    const float4 s = reinterpret_cast<const float4*>(sc)[c4];
    const float4 t = reinterpret_cast<const float4*>(sh)[c4];
    v.x = fmaxf(0.f, fmaf(v.x, s.x, t.x));
    v.y = fmaxf(0.f, fmaf(v.y, s.y, t.y));
    v.z = fmaxf(0.f, fmaf(v.z, s.z, t.z));
    v.w = fmaxf(0.f, fmaf(v.w, s.w, t.w));
    reinterpret_cast<float4*>(y)[i] = v;
}

// ---------------------------------------------------------------------------
// Tensor-core gather-GEMM. CTA: 128 rows x 128 cols. 16 warps; warp (wr,wc)
// owns a 16x64 sub-tile = 8 m16n8k8 mmas. A gathered into double-buffered
// SMEM via cp.async (zero-fill for missing neighbors); tf32 rounding applied
// in-register after the SMEM load. B-frags stream from pre-reordered weights
// (one coalesced LDG.64 per frag, L1-cached across row-warps).
// Emits per-channel (Sx, Sx^2) partials for BN.
// SMEM row pad +4 words => frag LDS bank = (4g + tg + c) mod 32: conflict-free.
// ---------------------------------------------------------------------------
template<int CIN>
__global__ __launch_bounds__(NTH)
void conv_mma(const float* __restrict__ X,     // [n, CIN] fp32
              const float* __restrict__ Wp,    // fragment-ordered weights
              const int*   __restrict__ nbr,   // [K, n] or nullptr (identity)
              int K, int n,
              float* __restrict__ out,         // [n, COUT] fp32
              float* __restrict__ partial)     // [nb, 256] (Sx | Sxx)
{
    constexpr int STRIDE = CIN + 4;            // padded SMEM row (words)
    constexpr int V      = CIN / 4;            // float4 per row
    constexpr int KC     = CIN / 8;            // k-chunks per offset
    extern __shared__ float sA[];              // [2][ROWS*STRIDE]

    const int tid  = threadIdx.x;
    const int lane = tid & 31, warp = tid >> 5;
    const int wr   = warp & 7,  wc  = warp >> 3;
    const int g    = lane >> 2, tg  = lane & 3;
    const int base = blockIdx.x * ROWS;
    const uint32_t sbase = (uint32_t)__cvta_generic_to_shared(sA);

    float acc[8][4];
#pragma unroll
    for (int i = 0; i < 8; ++i)
#pragma unroll
        for (int j = 0; j < 4; ++j) acc[i][j] = 0.f;

    // -- async gather of offset k into buffer (k&1); zero-fill OOB/missing --
    auto issue = [&](int k) {
        const uint32_t dst0 = sbase + (uint32_t)(k & 1) * (ROWS * STRIDE * 4);
#pragma unroll
        for (int i = 0; i < ROWS * V / NTH; ++i) {
            const int e   = tid + i * NTH;
            const int r   = e / V;
            const int c4  = e - r * V;
            const int row = base + r;
            int idx = -1;
            if (row < n)
                idx = nbr ? __ldg(&nbr[(size_t)k * n + row]) : row;
            const float* src = X + (size_t)(idx < 0 ? 0 : idx) * CIN + c4 * 4;
            cp16(dst0 + (uint32_t)(r * STRIDE + c4 * 4) * 4, src,
                 idx >= 0 ? 16 : 0);
        }
        cp_commit();
    };

    issue(0);
    const int r0 = wr * 16 + g;

    for (int k = 0; k < K; ++k) {
        cp_wait_all();
        __syncthreads();                 // buf k&1 ready
        if (k + 1 < K) issue(k + 1);     // overlap next gather with compute

        const float* A = sA + (k & 1) * (ROWS * STRIDE);
        const float2* Bp = reinterpret_cast<const float2*>(Wp)
                         + ((size_t)k * KC * 16 + wc * 8) * 32 + lane;
#pragma unroll 4
        for (int kc = 0; kc < KC; ++kc) {
            const int c0 = kc * 8 + tg;
            const uint32_t a0 = tf32u(A[r0 * STRIDE + c0]);
            const uint32_t a1 = tf32u(A[(r0 + 8) * STRIDE + c0]);
            const uint32_t a2 = tf32u(A[r0 * STRIDE + c0 + 4]);
            const uint32_t a3 = tf32u(A[(r0 + 8) * STRIDE + c0 + 4]);
            const float2* Bk = Bp + (size_t)kc * 16 * 32;
#pragma unroll
            for (int nt = 0; nt < 8; ++nt) {
                const float2 bv = __ldg(&Bk[nt * 32]);
                mma_tf32(acc[nt], a0, a1, a2, a3,
                         __float_as_uint(bv.x), __float_as_uint(bv.y));
            }
        }
    }

    // ---- store conv output ----
#pragma unroll
    for (int nt = 0; nt < 8; ++nt) {
        const int col = wc * 64 + nt * 8 + 2 * tg;
        const int row = base + r0;
        if (row < n)
            *reinterpret_cast<float2*>(out + (size_t)row * COUT + col) =
                make_float2(acc[nt][0], acc[nt][1]);
        if (row + 8 < n)
            *reinterpret_cast<float2*>(out + (size_t)(row + 8) * COUT + col) =
                make_float2(acc[nt][2], acc[nt][3]);
    }

    // ---- deterministic per-channel partials (Sx, Sx^2) ----
    // (zero-filled tail rows contribute exact zeros)
    float s[8][2], q[8][2];
#pragma unroll
    for (int nt = 0; nt < 8; ++nt) {
        s[nt][0] = acc[nt][0] + acc[nt][2];
        s[nt][1] = acc[nt][1] + acc[nt][3];
        q[nt][0] = acc[nt][0] * acc[nt][0] + acc[nt][2] * acc[nt][2];
        q[nt][1] = acc[nt][1] * acc[nt][1] + acc[nt][3] * acc[nt][3];
    }
#pragma unroll
    for (int off = 4; off <= 16; off <<= 1)      // reduce over g (8 lanes)
#pragma unroll
        for (int nt = 0; nt < 8; ++nt)
#pragma unroll
            for (int j = 0; j < 2; ++j) {
                s[nt][j] += __shfl_xor_sync(0xffffffffu, s[nt][j], off);
                q[nt][j] += __shfl_xor_sync(0xffffffffu, q[nt][j], off);
            }

    __syncthreads();                              // everyone done with sA
    float* sS = sA;                               // [wc:2][wr:8][64]
    float* sQ = sA + 1024;
    if (lane < 4) {
#pragma unroll
        for (int nt = 0; nt < 8; ++nt) {
            const int col = nt * 8 + 2 * tg;
            sS[wc * 512 + wr * 64 + col]     = s[nt][0];
            sS[wc * 512 + wr * 64 + col + 1] = s[nt][1];
            sQ[wc * 512 + wr * 64 + col]     = q[nt][0];
            sQ[wc * 512 + wr * 64 + col + 1] = q[nt][1];
        }
    }
    __syncthreads();
    if (tid < 128) {
        const int c = tid;
        float t = 0.f;
#pragma unroll
        for (int w = 0; w < 8; ++w)
            t += sS[(c >> 6) * 512 + w * 64 + (c & 63)];
        partial[(size_t)blockIdx.x * 256 + c] = t;
    } else if (tid < 256) {
        const int c = tid - 128;
        float t = 0.f;
#pragma unroll
        for (int w = 0; w < 8; ++w)
            t += sQ[(c >> 6) * 512 + w * 64 + (c & 63)];
        partial[(size_t)blockIdx.x * 256 + 128 + c] = t;
    }
}

// ---------------------------------------------------------------------------
// Parallel BN finalize: 128 blocks (one per channel) x 256 threads.
// scale = gamma*rsqrt(var+eps), shift = beta - mean*scale.
// ---------------------------------------------------------------------------
__global__ void bn_finalize(const float* __restrict__ partial, int nb, int n,
                            const float* __restrict__ gamma,
                            const float* __restrict__ beta,
                            float* __restrict__ scale,
                            float* __restrict__ shift)
{
    const int c = blockIdx.x;
    const int t = threadIdx.x;
    __shared__ double rS[256], rQ[256];
    double S = 0.0, Q = 0.0;
    for (int b = t; b < nb; b += 256) {
        S += (double)partial[(size_t)b * 256 + c];
        Q += (double)partial[(size_t)b * 256 + 128 + c];
    }
    rS[t] = S; rQ[t] = Q;
    __syncthreads();
    for (int off = 128; off > 0; off >>= 1) {
        if (t < off) { rS[t] += rS[t + off]; rQ[t] += rQ[t + off]; }
        __syncthreads();
    }
    if (t == 0) {
        const double mean = rS[0] / n;
        const double var  = rQ[0] / n - mean * mean;
        const float  r    = rsqrtf((float)var + EPS_BN);
        const float  sc   = gamma[c] * r;
        scale[c] = sc;
        shift[c] = beta[c] - (float)mean * sc;
    }
}

// out = relu( h2*sc2 + sh2 + sk*scd + shd )
__global__ void final_kernel(const float* __restrict__ h2,
                             const float* __restrict__ sk,
                             const float* __restrict__ sc2,
                             const float* __restrict__ sh2,
                             const float* __restrict__ scd,
                             const float* __restrict__ shd,
                             float* __restrict__ out, int total4)
{
    const int i = blockIdx.x * blockDim.x + threadIdx.x;
    if (i >= total4) return;
    const int c4 = i & 31;
    const float4 a  = reinterpret_cast<const float4*>(h2)[i];
    const float4 b  = reinterpret_cast<const float4*>(sk)[i];
    const float4 s2 = reinterpret_cast<const float4*>(sc2)[c4];
    const float4 t2 = reinterpret_cast<const float4*>(sh2)[c4];
    const float4 sd = reinterpret_cast<const float4*>(scd)[c4];
    const float4 td = reinterpret_cast<const float4*>(shd)[c4];
    float4 v;
    v.x = fmaxf(0.f, fmaf(a.x, s2.x, t2.x) + fmaf(b.x, sd.x, td.x));
    v.y = fmaxf(0.f, fmaf(a.y, s2.y, t2.y) + fmaf(b.y, sd.y, td.y));
    v.z = fmaxf(0.f, fmaf(a.z, s2.z, t2.z) + fmaf(b.z, sd.z, td.z));
    v.w = fmaxf(0.f, fmaf(a.w, s2.w, t2.w) + fmaf(b.w, sd.w, td.w));
    reinterpret_cast<float4*>(out)[i] = v;
}

// ---------------------------------------------------------------------------
extern "C" void kernel_launch(void* const* d_in, const int* in_sizes, int n_in,
                              void* d_out, int out_size)
{
    const float* feats = (const float*)d_in[0];
    const int*   nbr1  = (const int*)  d_in[1];
    const int*   nbr2  = (const int*)  d_in[2];
    const float* W1    = (const float*)d_in[3];
    const float* W2    = (const float*)d_in[4];
    const float* Wd    = (const float*)d_in[5];
    const float* g1    = (const float*)d_in[6];
    const float* b1    = (const float*)d_in[7];
    const float* g2    = (const float*)d_in[8];
    const float* b2    = (const float*)d_in[9];
    const float* gd    = (const float*)d_in[10];
    const float* bd    = (const float*)d_in[11];
    float* out = (float*)d_out;

    const int n  = in_sizes[0] / 64;      // 200000
    const int K  = in_sizes[1] / n;       // 27
    const int nb = (n + ROWS - 1) / ROWS; // 1563

    float *h1, *h1t, *h2, *sk, *wp1, *wp2, *wpd, *p1, *p2, *pd;
    float *sc1, *sh1, *sc2, *sh2, *scd, *shd;
    cudaGetSymbolAddress((void**)&h1,  g_h1);
    cudaGetSymbolAddress((void**)&h1t, g_h1t);
    cudaGetSymbolAddress((void**)&h2,  g_h2);
    cudaGetSymbolAddress((void**)&sk,  g_sk);
    cudaGetSymbolAddress((void**)&wp1, g_wp1);
    cudaGetSymbolAddress((void**)&wp2, g_wp2);
    cudaGetSymbolAddress((void**)&wpd, g_wpd);
    cudaGetSymbolAddress((void**)&p1,  g_part1);
    cudaGetSymbolAddress((void**)&p2,  g_part2);
    cudaGetSymbolAddress((void**)&pd,  g_partd);
    cudaGetSymbolAddress((void**)&sc1, g_sc1);
    cudaGetSymbolAddress((void**)&sh1, g_sh1);
    cudaGetSymbolAddress((void**)&sc2, g_sc2);
    cudaGetSymbolAddress((void**)&sh2, g_sh2);
    cudaGetSymbolAddress((void**)&scd, g_scd);
    cudaGetSymbolAddress((void**)&shd, g_shd);

    const int smem64  = 2 * ROWS * (64 + 4)  * 4;   //  69632 B
    const int smem128 = 2 * ROWS * (128 + 4) * 4;   // 135168 B
    cudaFuncSetAttribute(conv_mma<64>,
        cudaFuncAttributeMaxDynamicSharedMemorySize, smem64);
    cudaFuncSetAttribute(conv_mma<128>,
        cudaFuncAttributeMaxDynamicSharedMemorySize, smem128);

    // ---- weight reorder into fragment order ----
    {
        int t1 = K * (64 / 8)  * 16 * 32;
        int t2 = K * (128 / 8) * 16 * 32;
        int td = 1 * (64 / 8)  * 16 * 32;
        prep_w<<<(t1 + 255) / 256, 256>>>(W1, wp1, K, 64);
        prep_w<<<(t2 + 255) / 256, 256>>>(W2, wp2, K, 128);
        prep_w<<<(td + 255) / 256, 256>>>(Wd, wpd, 1, 64);
    }

    // conv1 + BN1 partials
    conv_mma<64><<<nb, NTH, smem64>>>(feats, wp1, nbr1, K, n, h1, p1);
    // skip (identity gather, K=1) + BNd partials
    conv_mma<64><<<nb, NTH, smem64>>>(feats, wpd, nullptr, 1, n, sk, pd);
    bn_finalize<<<128, 256>>>(p1, nb, n, g1, b1, sc1, sh1);
    bn_finalize<<<128, 256>>>(pd, nb, n, gd, bd, scd, shd);
    // h1t = relu(BN1(h1))  (tf32 rounding happens inside conv2)
    const int t4 = n * (COUT / 4);
    bn_relu<<<(t4 + 511) / 512, 512>>>(h1, sc1, sh1, h1t, t4);
    // conv2 + BN2 partials
    conv_mma<128><<<nb, NTH, smem128>>>(h1t, wp2, nbr2, K, n, h2, p2);
    bn_finalize<<<128, 256>>>(p2, nb, n, g2, b2, sc2, sh2);
    // out = relu(BN2(h2) + BNd(sk))
    final_kernel<<<(t4 + 511) / 512, 512>>>(h2, sk, sc2, sh2,
                                            scd, shd, out, t4);
}

// round 6
// speedup vs baseline: 1.8606x; 1.8606x over previous
#include <cuda_runtime.h>
#include <cstdint>

// ---------------------------------------------------------------------------
// SparseResBlock on sm_103a — tf32 mma.sync, 64-row CTA tiles,
// ldmatrix A-frags + paired B-frag LDG.128.
//   h   = ReLU(BN1(spconv(x, W1, nbr1)))
//   h2  = BN2(spconv(h, W2, nbr2))
//   out = ReLU(h2 + BNd(x @ Wd))
// N=200000, Cin=64, Cout=128, K=27.
// ---------------------------------------------------------------------------

#define EPS_BN 1e-5f

constexpr int COUT   = 128;
constexpr int ROWS   = 64;        // output rows per CTA
constexpr int NTH    = 256;       // 8 warps: 4 row-warps x 2 col-warps
constexpr int MAXN   = 200000;
constexpr int MAXBLK = (MAXN + ROWS - 1) / ROWS;   // 3125

// ---- device-global scratch (no allocation allowed in kernel_launch) ----
__device__ float g_h1 [(size_t)MAXN * COUT];  // conv1 raw fp32
__device__ float g_h1t[(size_t)MAXN * COUT];  // relu(BN1(h1)), tf32-rounded
__device__ float g_h2 [(size_t)MAXN * COUT];  // conv2 raw fp32
__device__ float g_sk [(size_t)MAXN * COUT];  // skip raw fp32
__device__ float g_xt [(size_t)MAXN * 64];    // feats, tf32-rounded
__device__ float g_wp1[27 * 64  * 128];       // W1, paired-fragment order
__device__ float g_wp2[27 * 128 * 128];       // W2, paired-fragment order
__device__ float g_wpd[64 * 128];             // Wd, paired-fragment order
__device__ float g_part1[(size_t)MAXBLK * 256];
__device__ float g_part2[(size_t)MAXBLK * 256];
__device__ float g_partd[(size_t)MAXBLK * 256];
__device__ float g_sc1[COUT], g_sh1[COUT];
__device__ float g_sc2[COUT], g_sh2[COUT];
__device__ float g_scd[COUT], g_shd[COUT];

// ---------------------------------------------------------------------------
__device__ __forceinline__ float tf32r(float x) {
    uint32_t u;
    asm("cvt.rna.tf32.f32 %0, %1;" : "=r"(u) : "f"(x));
    return __uint_as_float(u);
}

__device__ __forceinline__ void cp16(uint32_t dst, const void* src, int sz) {
    // cp.async 16B with runtime src-size (0 => zero-fill)
    asm volatile("cp.async.cg.shared.global [%0], [%1], 16, %2;\n"
                 :: "r"(dst), "l"(src), "r"(sz));
}
__device__ __forceinline__ void cp_commit() {
    asm volatile("cp.async.commit_group;\n" ::: "memory");
}
__device__ __forceinline__ void cp_wait_all() {
    asm volatile("cp.async.wait_group 0;\n" ::: "memory");
}

// ldmatrix x4: loads the full m16k8 tf32 A fragment (a0..a3) in one op.
__device__ __forceinline__ void ldsm_x4(uint32_t& a0, uint32_t& a1,
                                        uint32_t& a2, uint32_t& a3,
                                        uint32_t addr) {
    asm volatile("ldmatrix.sync.aligned.m8n8.x4.shared.b16 "
                 "{%0,%1,%2,%3}, [%4];"
                 : "=r"(a0), "=r"(a1), "=r"(a2), "=r"(a3) : "r"(addr));
}

__device__ __forceinline__ void mma_tf32(float acc[4],
                                         uint32_t a0, uint32_t a1,
                                         uint32_t a2, uint32_t a3,
                                         uint32_t b0, uint32_t b1) {
    asm volatile(
        "mma.sync.aligned.m16n8k8.row.col.f32.tf32.tf32.f32 "
        "{%0,%1,%2,%3}, {%4,%5,%6,%7}, {%8,%9}, {%0,%1,%2,%3};\n"
        : "+f"(acc[0]), "+f"(acc[1]), "+f"(acc[2]), "+f"(acc[3])
        : "r"(a0), "r"(a1), "r"(a2), "r"(a3), "r"(b0), "r"(b1));
}

// ---------------------------------------------------------------------------
// Weight reorder: W[K][CIN][128] -> PAIRED m16n8k8 .row.col fragment order.
// float4 at index ((k*KC + kc)*8 + p)*32 + lane  (p = 0..7, nt = 2p, 2p+1):
//   { W[k][kc*8+lane%4][2p*8   + lane/4], W[k][kc*8+lane%4+4][2p*8   + lane/4],
//     W[k][kc*8+lane%4][(2p+1)*8+lane/4], W[k][kc*8+lane%4+4][(2p+1)*8+lane/4] }
// (tf32-rounded) so one LDG.128 per lane feeds TWO mmas.
// ---------------------------------------------------------------------------
__global__ void prep_w(const float* __restrict__ W, float* __restrict__ Wp,
                       int K, int CIN)
{
    const int KC    = CIN / 8;
    const int total = K * KC * 8 * 32;
    const int gid   = blockIdx.x * blockDim.x + threadIdx.x;
    if (gid >= total) return;
    const int lane = gid & 31;
    int t = gid >> 5;
    const int p  = t & 7;  t >>= 3;
    const int kc = t % KC;
    const int k  = t / KC;
    const int row  = kc * 8 + (lane & 3);
    const int col0 = (2 * p)     * 8 + (lane >> 2);
    const int col1 = (2 * p + 1) * 8 + (lane >> 2);
    const size_t b0 = ((size_t)k * CIN + row) * COUT;
    float4 v;
    v.x = tf32r(W[b0 + col0]);
    v.y = tf32r(W[b0 + 4 * COUT + col0]);
    v.z = tf32r(W[b0 + col1]);
    v.w = tf32r(W[b0 + 4 * COUT + col1]);
    reinterpret_cast<float4*>(Wp)[gid] = v;
}

// elementwise: y = tf32(x)
__global__ void cvt_kernel(const float* __restrict__ x, float* __restrict__ y,
                           int total4)
{
    const int i = blockIdx.x * blockDim.x + threadIdx.x;
    if (i >= total4) return;
    float4 v = reinterpret_cast<const float4*>(x)[i];
    v.x = tf32r(v.x); v.y = tf32r(v.y); v.z = tf32r(v.z); v.w = tf32r(v.w);
    reinterpret_cast<float4*>(y)[i] = v;
}

// elementwise: y = tf32(relu(x*sc + sh)), per-channel sc/sh (COUT=128)
__global__ void bn_relu_cvt(const float* __restrict__ x,
                            const float* __restrict__ sc,
                            const float* __restrict__ sh,
                            float* __restrict__ y, int total4)
{
    const int i = blockIdx.x * blockDim.x + threadIdx.x;
    if (i >= total4) return;
    const int c4 = i & 31;
    float4 v = reinterpret_cast<const float4*>(x)[i];
    const float4 s = reinterpret_cast<const float4*>(sc)[c4];
    const float4 t = reinterpret_cast<const float4*>(sh)[c4];
    v.x = tf32r(fmaxf(0.f, fmaf(v.x, s.x, t.x)));
    v.y = tf32r(fmaxf(0.f, fmaf(v.y, s.y, t.y)));
    v.z = tf32r(fmaxf(0.f, fmaf(v.z, s.z, t.z)));
    v.w = tf32r(fmaxf(0.f, fmaf(v.w, s.w, t.w)));
    reinterpret_cast<float4*>(y)[i] = v;
}

// ---------------------------------------------------------------------------
// Tensor-core gather-GEMM. CTA: 64 rows x 128 cols. 8 warps; warp (wr,wc)
// owns 16x64 = 8 m16n8k8 mmas. A gathered into double-buffered SMEM via
// cp.async (zero-fill for missing neighbors), A-frags via one ldmatrix.x4
// per kc, B via 4 paired LDG.128 per kc. Emits (Sx, Sx^2) BN partials.
// STRIDE = CIN+4 => ldmatrix rows land 4 banks apart: conflict-free.
// ---------------------------------------------------------------------------
template<int CIN>
__global__ __launch_bounds__(NTH, 3)
void conv_mma(const float* __restrict__ X,     // [n, CIN], tf32-rounded
              const float* __restrict__ Wp,    // paired-fragment weights
              const int*   __restrict__ nbr,   // [K, n] or nullptr (identity)
              int K, int n,
              float* __restrict__ out,         // [n, COUT] fp32
              float* __restrict__ partial)     // [nb, 256] (Sx | Sxx)
{
    constexpr int STRIDE = CIN + 4;            // padded SMEM row (words)
    constexpr int V      = CIN / 4;            // float4 per row
    constexpr int KC     = CIN / 8;            // k-chunks per offset
    extern __shared__ float sA[];              // [2][ROWS*STRIDE]

    const int tid  = threadIdx.x;
    const int lane = tid & 31, warp = tid >> 5;
    const int wr   = warp & 3,  wc  = warp >> 2;
    const int g    = lane >> 2, tg  = lane & 3;
    const int base = blockIdx.x * ROWS;
    const uint32_t sbase = (uint32_t)__cvta_generic_to_shared(sA);

    // per-lane ldmatrix address (kc=0, buffer 0):
    //   mat = lane/8 (0:a0 1:a1 2:a2 3:a3), r = lane%8
    //   row = wr*16 + (mat&1)*8 + r, colbase = (mat>>1)*4
    const int mat = lane >> 3, mr = lane & 7;
    const uint32_t lds0 = sbase +
        (uint32_t)(((wr * 16 + (mat & 1) * 8 + mr) * STRIDE
                    + (mat >> 1) * 4) * 4);

    float acc[8][4];
#pragma unroll
    for (int i = 0; i < 8; ++i)
#pragma unroll
        for (int j = 0; j < 4; ++j) acc[i][j] = 0.f;

    // -- async gather of offset k into buffer (k&1); zero-fill missing --
    auto issue = [&](int k) {
        const uint32_t dst0 = sbase + (uint32_t)(k & 1) * (ROWS * STRIDE * 4);
#pragma unroll
        for (int i = 0; i < ROWS * V / NTH; ++i) {
            const int e   = tid + i * NTH;
            const int r   = e / V;
            const int c4  = e - r * V;
            const int row = base + r;
            int idx = -1;
            if (row < n)
                idx = nbr ? __ldg(&nbr[(size_t)k * n + row]) : row;
            const float* src = X + (size_t)(idx < 0 ? 0 : idx) * CIN + c4 * 4;
            cp16(dst0 + (uint32_t)(r * STRIDE + c4 * 4) * 4, src,
                 idx >= 0 ? 16 : 0);
        }
        cp_commit();
    };

    issue(0);

    for (int k = 0; k < K; ++k) {
        cp_wait_all();
        __syncthreads();                 // buf k&1 ready
        if (k + 1 < K) issue(k + 1);     // overlap next gather with compute

        const uint32_t abase = lds0 + (uint32_t)(k & 1) * (ROWS * STRIDE * 4);
        const float4* Bp = reinterpret_cast<const float4*>(Wp)
                         + ((size_t)k * KC * 8 + wc * 4) * 32 + lane;
#pragma unroll 4
        for (int kc = 0; kc < KC; ++kc) {
            uint32_t a0, a1, a2, a3;
            ldsm_x4(a0, a1, a2, a3, abase + kc * 32);
            const float4* Bk = Bp + (size_t)kc * 8 * 32;
#pragma unroll
            for (int p = 0; p < 4; ++p) {
                const float4 bv = __ldg(&Bk[p * 32]);
                mma_tf32(acc[2 * p],     a0, a1, a2, a3,
                         __float_as_uint(bv.x), __float_as_uint(bv.y));
                mma_tf32(acc[2 * p + 1], a0, a1, a2, a3,
                         __float_as_uint(bv.z), __float_as_uint(bv.w));
            }
        }
    }

    // ---- store conv output ----
    const int r0 = wr * 16 + g;
#pragma unroll
    for (int nt = 0; nt < 8; ++nt) {
        const int col = wc * 64 + nt * 8 + 2 * tg;
        const int row = base + r0;
        if (row < n)
            *reinterpret_cast<float2*>(out + (size_t)row * COUT + col) =
                make_float2(acc[nt][0], acc[nt][1]);
        if (row + 8 < n)
            *reinterpret_cast<float2*>(out + (size_t)(row + 8) * COUT + col) =
                make_float2(acc[nt][2], acc[nt][3]);
    }

    // ---- deterministic per-channel partials (Sx, Sx^2) ----
    float s[8][2], q[8][2];
#pragma unroll
    for (int nt = 0; nt < 8; ++nt) {
        s[nt][0] = acc[nt][0] + acc[nt][2];
        s[nt][1] = acc[nt][1] + acc[nt][3];
        q[nt][0] = acc[nt][0] * acc[nt][0] + acc[nt][2] * acc[nt][2];
        q[nt][1] = acc[nt][1] * acc[nt][1] + acc[nt][3] * acc[nt][3];
    }
#pragma unroll
    for (int off = 4; off <= 16; off <<= 1)      // reduce over g (8 lanes)
#pragma unroll
        for (int nt = 0; nt < 8; ++nt)
#pragma unroll
            for (int j = 0; j < 2; ++j) {
                s[nt][j] += __shfl_xor_sync(0xffffffffu, s[nt][j], off);
                q[nt][j] += __shfl_xor_sync(0xffffffffu, q[nt][j], off);
            }

    __syncthreads();                              // everyone done with sA
    float* sS = sA;                               // [wc:2][wr:4][64]
    float* sQ = sA + 512;
    if (lane < 4) {
#pragma unroll
        for (int nt = 0; nt < 8; ++nt) {
            const int col = nt * 8 + 2 * tg;
            sS[wc * 256 + wr * 64 + col]     = s[nt][0];
            sS[wc * 256 + wr * 64 + col + 1] = s[nt][1];
            sQ[wc * 256 + wr * 64 + col]     = q[nt][0];
            sQ[wc * 256 + wr * 64 + col + 1] = q[nt][1];
        }
    }
    __syncthreads();
    if (tid < 128) {
        const int c = tid;
        float t = 0.f;
#pragma unroll
        for (int w = 0; w < 4; ++w) t += sS[(c >> 6) * 256 + w * 64 + (c & 63)];
        partial[(size_t)blockIdx.x * 256 + c] = t;
    } else {
        const int c = tid - 128;
        float t = 0.f;
#pragma unroll
        for (int w = 0; w < 4; ++w) t += sQ[(c >> 6) * 256 + w * 64 + (c & 63)];
        partial[(size_t)blockIdx.x * 256 + 128 + c] = t;
    }
}

// ---------------------------------------------------------------------------
// Parallel BN finalize: 128 blocks (one per channel) x 256 threads.
// ---------------------------------------------------------------------------
__global__ void bn_finalize(const float* __restrict__ partial, int nb, int n,
                            const float* __restrict__ gamma,
                            const float* __restrict__ beta,
                            float* __restrict__ scale,
                            float* __restrict__ shift)
{
    const int c = blockIdx.x;
    const int t = threadIdx.x;
    __shared__ double rS[256], rQ[256];
    double S = 0.0, Q = 0.0;
    for (int b = t; b < nb; b += 256) {
        S += (double)partial[(size_t)b * 256 + c];
        Q += (double)partial[(size_t)b * 256 + 128 + c];
    }
    rS[t] = S; rQ[t] = Q;
    __syncthreads();
    for (int off = 128; off > 0; off >>= 1) {
        if (t < off) { rS[t] += rS[t + off]; rQ[t] += rQ[t + off]; }
        __syncthreads();
    }
    if (t == 0) {
        const double mean = rS[0] / n;
        const double var  = rQ[0] / n - mean * mean;
        const float  r    = rsqrtf((float)var + EPS_BN);
        const float  sc   = gamma[c] * r;
        scale[c] = sc;
        shift[c] = beta[c] - (float)mean * sc;
    }
}

// out = relu( h2*sc2 + sh2 + sk*scd + shd )
__global__ void final_kernel(const float* __restrict__ h2,
                             const float* __restrict__ sk,
                             const float* __restrict__ sc2,
                             const float* __restrict__ sh2,
                             const float* __restrict__ scd,
                             const float* __restrict__ shd,
                             float* __restrict__ out, int total4)
{
    const int i = blockIdx.x * blockDim.x + threadIdx.x;
    if (i >= total4) return;
    const int c4 = i & 31;
    const float4 a  = reinterpret_cast<const float4*>(h2)[i];
    const float4 b  = reinterpret_cast<const float4*>(sk)[i];
    const float4 s2 = reinterpret_cast<const float4*>(sc2)[c4];
    const float4 t2 = reinterpret_cast<const float4*>(sh2)[c4];
    const float4 sd = reinterpret_cast<const float4*>(scd)[c4];
    const float4 td = reinterpret_cast<const float4*>(shd)[c4];
    float4 v;
    v.x = fmaxf(0.f, fmaf(a.x, s2.x, t2.x) + fmaf(b.x, sd.x, td.x));
    v.y = fmaxf(0.f, fmaf(a.y, s2.y, t2.y) + fmaf(b.y, sd.y, td.y));
    v.z = fmaxf(0.f, fmaf(a.z, s2.z, t2.z) + fmaf(b.z, sd.z, td.z));
    v.w = fmaxf(0.f, fmaf(a.w, s2.w, t2.w) + fmaf(b.w, sd.w, td.w));
    reinterpret_cast<float4*>(out)[i] = v;
}

// ---------------------------------------------------------------------------
extern "C" void kernel_launch(void* const* d_in, const int* in_sizes, int n_in,
                              void* d_out, int out_size)
{
    const float* feats = (const float*)d_in[0];
    const int*   nbr1  = (const int*)  d_in[1];
    const int*   nbr2  = (const int*)  d_in[2];
    const float* W1    = (const float*)d_in[3];
    const float* W2    = (const float*)d_in[4];
    const float* Wd    = (const float*)d_in[5];
    const float* g1    = (const float*)d_in[6];
    const float* b1    = (const float*)d_in[7];
    const float* g2    = (const float*)d_in[8];
    const float* b2    = (const float*)d_in[9];
    const float* gd    = (const float*)d_in[10];
    const float* bd    = (const float*)d_in[11];
    float* out = (float*)d_out;

    const int n  = in_sizes[0] / 64;      // 200000
    const int K  = in_sizes[1] / n;       // 27
    const int nb = (n + ROWS - 1) / ROWS; // 3125

    float *h1, *h1t, *h2, *sk, *xt, *wp1, *wp2, *wpd, *p1, *p2, *pd;
    float *sc1, *sh1, *sc2, *sh2, *scd, *shd;
    cudaGetSymbolAddress((void**)&h1,  g_h1);
    cudaGetSymbolAddress((void**)&h1t, g_h1t);
    cudaGetSymbolAddress((void**)&h2,  g_h2);
    cudaGetSymbolAddress((void**)&sk,  g_sk);
    cudaGetSymbolAddress((void**)&xt,  g_xt);
    cudaGetSymbolAddress((void**)&wp1, g_wp1);
    cudaGetSymbolAddress((void**)&wp2, g_wp2);
    cudaGetSymbolAddress((void**)&wpd, g_wpd);
    cudaGetSymbolAddress((void**)&p1,  g_part1);
    cudaGetSymbolAddress((void**)&p2,  g_part2);
    cudaGetSymbolAddress((void**)&pd,  g_partd);
    cudaGetSymbolAddress((void**)&sc1, g_sc1);
    cudaGetSymbolAddress((void**)&sh1, g_sh1);
    cudaGetSymbolAddress((void**)&sc2, g_sc2);
    cudaGetSymbolAddress((void**)&sh2, g_sh2);
    cudaGetSymbolAddress((void**)&scd, g_scd);
    cudaGetSymbolAddress((void**)&shd, g_shd);

    const int smem64  = 2 * ROWS * (64 + 4)  * 4;   // 34816 B
    const int smem128 = 2 * ROWS * (128 + 4) * 4;   // 67584 B
    cudaFuncSetAttribute(conv_mma<64>,
        cudaFuncAttributeMaxDynamicSharedMemorySize, smem64);
    cudaFuncSetAttribute(conv_mma<128>,
        cudaFuncAttributeMaxDynamicSharedMemorySize, smem128);

    // ---- prep: tf32-round feats, reorder weights into paired-frag order ----
    const int xt4 = n * (64 / 4);
    cvt_kernel<<<(xt4 + 255) / 256, 256>>>(feats, xt, xt4);
    {
        int t1 = K * (64 / 8)  * 8 * 32;
        int t2 = K * (128 / 8) * 8 * 32;
        int td = 1 * (64 / 8)  * 8 * 32;
        prep_w<<<(t1 + 255) / 256, 256>>>(W1, wp1, K, 64);
        prep_w<<<(t2 + 255) / 256, 256>>>(W2, wp2, K, 128);
        prep_w<<<(td + 255) / 256, 256>>>(Wd, wpd, 1, 64);
    }

    // conv1 + BN1 partials
    conv_mma<64><<<nb, NTH, smem64>>>(xt, wp1, nbr1, K, n, h1, p1);
    // skip (identity gather, K=1) + BNd partials
    conv_mma<64><<<nb, NTH, smem64>>>(xt, wpd, nullptr, 1, n, sk, pd);
    bn_finalize<<<128, 256>>>(p1, nb, n, g1, b1, sc1, sh1);
    bn_finalize<<<128, 256>>>(pd, nb, n, gd, bd, scd, shd);
    // h1t = tf32(relu(BN1(h1)))
    const int t4 = n * (COUT / 4);
    bn_relu_cvt<<<(t4 + 255) / 256, 256>>>(h1, sc1, sh1, h1t, t4);
    // conv2 + BN2 partials
    conv_mma<128><<<nb, NTH, smem128>>>(h1t, wp2, nbr2, K, n, h2, p2);
    bn_finalize<<<128, 256>>>(p2, nb, n, g2, b2, sc2, sh2);
    // out = relu(BN2(h2) + BNd(sk))
    final_kernel<<<(t4 + 255) / 256, 256>>>(h2, sk, sc2, sh2,
                                            scd, shd, out, t4);
}

// round 7
// speedup vs baseline: 2.2668x; 1.2183x over previous
#include <cuda_runtime.h>
#include <cstdint>

// ---------------------------------------------------------------------------
// SparseResBlock on sm_103a — tf32 mma.sync, 64-row CTA tiles, row-paired
// warps (each B fragment feeds two m16 row tiles => L1 B-traffic halved).
//   h   = ReLU(BN1(spconv(x, W1, nbr1)))
//   h2  = BN2(spconv(h, W2, nbr2))
//   out = ReLU(h2 + BNd(x @ Wd))
// N=200000, Cin=64, Cout=128, K=27.
// ---------------------------------------------------------------------------

#define EPS_BN 1e-5f

constexpr int COUT   = 128;
constexpr int ROWS   = 64;        // output rows per CTA
constexpr int NTH    = 256;       // 8 warps: wr in {0,1} x wc in {0..3}
constexpr int MAXN   = 200000;
constexpr int MAXBLK = (MAXN + ROWS - 1) / ROWS;   // 3125

// ---- device-global scratch (no allocation allowed in kernel_launch) ----
__device__ float g_h1 [(size_t)MAXN * COUT];  // conv1 raw fp32
__device__ float g_h1t[(size_t)MAXN * COUT];  // relu(BN1(h1)), tf32-rounded
__device__ float g_h2 [(size_t)MAXN * COUT];  // conv2 raw fp32
__device__ float g_sk [(size_t)MAXN * COUT];  // skip raw fp32
__device__ float g_xt [(size_t)MAXN * 64];    // feats, tf32-rounded
__device__ float g_wp1[27 * 64  * 128];       // W1 in mma-fragment order
__device__ float g_wp2[27 * 128 * 128];       // W2 in mma-fragment order
__device__ float g_wpd[64 * 128];             // Wd in mma-fragment order
__device__ float g_part1[(size_t)MAXBLK * 256];
__device__ float g_part2[(size_t)MAXBLK * 256];
__device__ float g_partd[(size_t)MAXBLK * 256];
__device__ float g_sc1[COUT], g_sh1[COUT];
__device__ float g_sc2[COUT], g_sh2[COUT];
__device__ float g_scd[COUT], g_shd[COUT];

// ---------------------------------------------------------------------------
__device__ __forceinline__ float tf32r(float x) {
    uint32_t u;
    asm("cvt.rna.tf32.f32 %0, %1;" : "=r"(u) : "f"(x));
    return __uint_as_float(u);
}

__device__ __forceinline__ void cp16(uint32_t dst, const void* src, int sz) {
    // cp.async 16B with runtime src-size (0 => zero-fill)
    asm volatile("cp.async.cg.shared.global [%0], [%1], 16, %2;\n"
                 :: "r"(dst), "l"(src), "r"(sz));
}
__device__ __forceinline__ void cp_commit() {
    asm volatile("cp.async.commit_group;\n" ::: "memory");
}
__device__ __forceinline__ void cp_wait_all() {
    asm volatile("cp.async.wait_group 0;\n" ::: "memory");
}

__device__ __forceinline__ void mma_tf32(float acc[4],
                                         uint32_t a0, uint32_t a1,
                                         uint32_t a2, uint32_t a3,
                                         uint32_t b0, uint32_t b1) {
    asm volatile(
        "mma.sync.aligned.m16n8k8.row.col.f32.tf32.tf32.f32 "
        "{%0,%1,%2,%3}, {%4,%5,%6,%7}, {%8,%9}, {%0,%1,%2,%3};\n"
        : "+f"(acc[0]), "+f"(acc[1]), "+f"(acc[2]), "+f"(acc[3])
        : "r"(a0), "r"(a1), "r"(a2), "r"(a3), "r"(b0), "r"(b1));
}

// ---------------------------------------------------------------------------
// Weight reorder (round-4 layout): W[K][CIN][128] -> m16n8k8 .row.col frags:
//   float2 at ((k*KC + kc)*16 + nt)*32 + lane =
//     {W[k][kc*8 + lane%4    ][nt*8 + lane/4],
//      W[k][kc*8 + lane%4 + 4][nt*8 + lane/4]}   (tf32-rounded)
// One warp B-frag load = one coalesced 256B LDG.64.
// ---------------------------------------------------------------------------
__global__ void prep_w(const float* __restrict__ W, float* __restrict__ Wp,
                       int K, int CIN)
{
    const int KC    = CIN / 8;
    const int total = K * KC * 16 * 32;
    const int gid   = blockIdx.x * blockDim.x + threadIdx.x;
    if (gid >= total) return;
    const int lane = gid & 31;
    int t  = gid >> 5;
    const int nt = t & 15;  t >>= 4;
    const int kc = t % KC;
    const int k  = t / KC;
    const int row = kc * 8 + (lane & 3);
    const int col = nt * 8 + (lane >> 2);
    const size_t base = ((size_t)k * CIN + row) * COUT + col;
    Wp[(size_t)gid * 2]     = tf32r(W[base]);
    Wp[(size_t)gid * 2 + 1] = tf32r(W[base + 4 * COUT]);
}

// elementwise: y = tf32(x)
__global__ void cvt_kernel(const float* __restrict__ x, float* __restrict__ y,
                           int total4)
{
    const int i = blockIdx.x * blockDim.x + threadIdx.x;
    if (i >= total4) return;
    float4 v = reinterpret_cast<const float4*>(x)[i];
    v.x = tf32r(v.x); v.y = tf32r(v.y); v.z = tf32r(v.z); v.w = tf32r(v.w);
    reinterpret_cast<float4*>(y)[i] = v;
}

// elementwise: y = tf32(relu(x*sc + sh)), per-channel sc/sh (COUT=128)
__global__ void bn_relu_cvt(const float* __restrict__ x,
                            const float* __restrict__ sc,
                            const float* __restrict__ sh,
                            float* __restrict__ y, int total4)
{
    const int i = blockIdx.x * blockDim.x + threadIdx.x;
    if (i >= total4) return;
    const int c4 = i & 31;
    float4 v = reinterpret_cast<const float4*>(x)[i];
    const float4 s = reinterpret_cast<const float4*>(sc)[c4];
    const float4 t = reinterpret_cast<const float4*>(sh)[c4];
    v.x = tf32r(fmaxf(0.f, fmaf(v.x, s.x, t.x)));
    v.y = tf32r(fmaxf(0.f, fmaf(v.y, s.y, t.y)));
    v.z = tf32r(fmaxf(0.f, fmaf(v.z, s.z, t.z)));
    v.w = tf32r(fmaxf(0.f, fmaf(v.w, s.w, t.w)));
    reinterpret_cast<float4*>(y)[i] = v;
}

// ---------------------------------------------------------------------------
// Tensor-core gather-GEMM. CTA: 64 rows x 128 cols. 8 warps:
//   wr = warp&1  -> rows [wr*32, wr*32+32)  (two m16 tiles, t = 0/1)
//   wc = warp>>1 -> cols [wc*32, wc*32+32)  (four n8 tiles, p = 0..3)
// Per kc: 8 scalar LDS (A frags, conflict-free via +4 pad) + 4 LDG.64
// (B frags, EACH feeding TWO mmas) + 8 mma. A double-buffered in SMEM via
// cp.async zero-fill gather. Emits per-channel (Sx, Sx^2) BN partials.
// ---------------------------------------------------------------------------
template<int CIN>
__global__ __launch_bounds__(NTH, 3)
void conv_mma(const float* __restrict__ X,     // [n, CIN], tf32-rounded
              const float* __restrict__ Wp,    // fragment-ordered weights
              const int*   __restrict__ nbr,   // [K, n] or nullptr (identity)
              int K, int n,
              float* __restrict__ out,         // [n, COUT] fp32
              float* __restrict__ partial)     // [nb, 256] (Sx | Sxx)
{
    constexpr int STRIDE = CIN + 4;            // padded SMEM row (words)
    constexpr int V      = CIN / 4;            // float4 per row
    constexpr int KC     = CIN / 8;            // k-chunks per offset
    extern __shared__ float sA[];              // [2][ROWS*STRIDE]

    const int tid  = threadIdx.x;
    const int lane = tid & 31, warp = tid >> 5;
    const int wr   = warp & 1,  wc  = warp >> 1;
    const int g    = lane >> 2, tg  = lane & 3;
    const int base = blockIdx.x * ROWS;
    const uint32_t sbase = (uint32_t)__cvta_generic_to_shared(sA);

    float acc[2][4][4];                        // [row tile][n tile][frag]
#pragma unroll
    for (int t = 0; t < 2; ++t)
#pragma unroll
        for (int p = 0; p < 4; ++p)
#pragma unroll
            for (int j = 0; j < 4; ++j) acc[t][p][j] = 0.f;

    // -- async gather of offset k into buffer (k&1); zero-fill missing --
    auto issue = [&](int k) {
        const uint32_t dst0 = sbase + (uint32_t)(k & 1) * (ROWS * STRIDE * 4);
#pragma unroll
        for (int i = 0; i < ROWS * V / NTH; ++i) {
            const int e   = tid + i * NTH;
            const int r   = e / V;
            const int c4  = e - r * V;
            const int row = base + r;
            int idx = -1;
            if (row < n)
                idx = nbr ? __ldg(&nbr[(size_t)k * n + row]) : row;
            const float* src = X + (size_t)(idx < 0 ? 0 : idx) * CIN + c4 * 4;
            cp16(dst0 + (uint32_t)(r * STRIDE + c4 * 4) * 4, src,
                 idx >= 0 ? 16 : 0);
        }
        cp_commit();
    };

    issue(0);
    const int rA = wr * 32 + g;                // tile 0 base row (lane view)
    const int rB = rA + 16;                    // tile 1

    for (int k = 0; k < K; ++k) {
        cp_wait_all();
        __syncthreads();                 // buf k&1 ready
        if (k + 1 < K) issue(k + 1);     // overlap next gather with compute

        const float* A = sA + (k & 1) * (ROWS * STRIDE);
        const float2* Bp = reinterpret_cast<const float2*>(Wp)
                         + ((size_t)k * KC * 16 + wc * 4) * 32 + lane;
#pragma unroll 4
        for (int kc = 0; kc < KC; ++kc) {
            const int c0 = kc * 8 + tg;
            const uint32_t a0 = __float_as_uint(A[rA * STRIDE + c0]);
            const uint32_t a1 = __float_as_uint(A[(rA + 8) * STRIDE + c0]);
            const uint32_t a2 = __float_as_uint(A[rA * STRIDE + c0 + 4]);
            const uint32_t a3 = __float_as_uint(A[(rA + 8) * STRIDE + c0 + 4]);
            const uint32_t b0 = __float_as_uint(A[rB * STRIDE + c0]);
            const uint32_t b1 = __float_as_uint(A[(rB + 8) * STRIDE + c0]);
            const uint32_t b2 = __float_as_uint(A[rB * STRIDE + c0 + 4]);
            const uint32_t b3 = __float_as_uint(A[(rB + 8) * STRIDE + c0 + 4]);
            const float2* Bk = Bp + (size_t)kc * 16 * 32;
#pragma unroll
            for (int p = 0; p < 4; ++p) {
                const float2 bv = __ldg(&Bk[p * 32]);
                const uint32_t w0 = __float_as_uint(bv.x);
                const uint32_t w1 = __float_as_uint(bv.y);
                mma_tf32(acc[0][p], a0, a1, a2, a3, w0, w1);  // rows wr*32+..
                mma_tf32(acc[1][p], b0, b1, b2, b3, w0, w1);  // rows +16
            }
        }
    }

    // ---- store conv output ----
#pragma unroll
    for (int t = 0; t < 2; ++t) {
        const int row = base + wr * 32 + t * 16 + g;
#pragma unroll
        for (int p = 0; p < 4; ++p) {
            const int col = wc * 32 + p * 8 + 2 * tg;
            if (row < n)
                *reinterpret_cast<float2*>(out + (size_t)row * COUT + col) =
                    make_float2(acc[t][p][0], acc[t][p][1]);
            if (row + 8 < n)
                *reinterpret_cast<float2*>(out + (size_t)(row + 8) * COUT + col) =
                    make_float2(acc[t][p][2], acc[t][p][3]);
        }
    }

    // ---- deterministic per-channel partials (Sx, Sx^2) ----
    float s[4][2], q[4][2];
#pragma unroll
    for (int p = 0; p < 4; ++p)
#pragma unroll
        for (int j = 0; j < 2; ++j) {
            s[p][j] = acc[0][p][j] + acc[0][p][j + 2]
                    + acc[1][p][j] + acc[1][p][j + 2];
            q[p][j] = acc[0][p][j]     * acc[0][p][j]
                    + acc[0][p][j + 2] * acc[0][p][j + 2]
                    + acc[1][p][j]     * acc[1][p][j]
                    + acc[1][p][j + 2] * acc[1][p][j + 2];
        }
#pragma unroll
    for (int off = 4; off <= 16; off <<= 1)      // reduce over g (8 lanes)
#pragma unroll
        for (int p = 0; p < 4; ++p)
#pragma unroll
            for (int j = 0; j < 2; ++j) {
                s[p][j] += __shfl_xor_sync(0xffffffffu, s[p][j], off);
                q[p][j] += __shfl_xor_sync(0xffffffffu, q[p][j], off);
            }

    __syncthreads();                              // everyone done with sA
    float* sS = sA;                               // [wr:2][128]
    float* sQ = sA + 256;                         // [wr:2][128]
    if (lane < 4) {                               // g == 0 lanes (tg = lane)
#pragma unroll
        for (int p = 0; p < 4; ++p) {
            const int col = wc * 32 + p * 8 + 2 * tg;
            sS[wr * 128 + col]     = s[p][0];
            sS[wr * 128 + col + 1] = s[p][1];
            sQ[wr * 128 + col]     = q[p][0];
            sQ[wr * 128 + col + 1] = q[p][1];
        }
    }
    __syncthreads();
    if (tid < 128) {
        partial[(size_t)blockIdx.x * 256 + tid] = sS[tid] + sS[128 + tid];
    } else {
        const int c = tid - 128;
        partial[(size_t)blockIdx.x * 256 + 128 + c] = sQ[c] + sQ[128 + c];
    }
}

// ---------------------------------------------------------------------------
// Parallel BN finalize: 128 blocks (one per channel) x 256 threads.
// ---------------------------------------------------------------------------
__global__ void bn_finalize(const float* __restrict__ partial, int nb, int n,
                            const float* __restrict__ gamma,
                            const float* __restrict__ beta,
                            float* __restrict__ scale,
                            float* __restrict__ shift)
{
    const int c = blockIdx.x;
    const int t = threadIdx.x;
    __shared__ double rS[256], rQ[256];
    double S = 0.0, Q = 0.0;
    for (int b = t; b < nb; b += 256) {
        S += (double)partial[(size_t)b * 256 + c];
        Q += (double)partial[(size_t)b * 256 + 128 + c];
    }
    rS[t] = S; rQ[t] = Q;
    __syncthreads();
    for (int off = 128; off > 0; off >>= 1) {
        if (t < off) { rS[t] += rS[t + off]; rQ[t] += rQ[t + off]; }
        __syncthreads();
    }
    if (t == 0) {
        const double mean = rS[0] / n;
        const double var  = rQ[0] / n - mean * mean;
        const float  r    = rsqrtf((float)var + EPS_BN);
        const float  sc   = gamma[c] * r;
        scale[c] = sc;
        shift[c] = beta[c] - (float)mean * sc;
    }
}

// out = relu( h2*sc2 + sh2 + sk*scd + shd )
__global__ void final_kernel(const float* __restrict__ h2,
                             const float* __restrict__ sk,
                             const float* __restrict__ sc2,
                             const float* __restrict__ sh2,
                             const float* __restrict__ scd,
                             const float* __restrict__ shd,
                             float* __restrict__ out, int total4)
{
    const int i = blockIdx.x * blockDim.x + threadIdx.x;
    if (i >= total4) return;
    const int c4 = i & 31;
    const float4 a  = reinterpret_cast<const float4*>(h2)[i];
    const float4 b  = reinterpret_cast<const float4*>(sk)[i];
    const float4 s2 = reinterpret_cast<const float4*>(sc2)[c4];
    const float4 t2 = reinterpret_cast<const float4*>(sh2)[c4];
    const float4 sd = reinterpret_cast<const float4*>(scd)[c4];
    const float4 td = reinterpret_cast<const float4*>(shd)[c4];
    float4 v;
    v.x = fmaxf(0.f, fmaf(a.x, s2.x, t2.x) + fmaf(b.x, sd.x, td.x));
    v.y = fmaxf(0.f, fmaf(a.y, s2.y, t2.y) + fmaf(b.y, sd.y, td.y));
    v.z = fmaxf(0.f, fmaf(a.z, s2.z, t2.z) + fmaf(b.z, sd.z, td.z));
    v.w = fmaxf(0.f, fmaf(a.w, s2.w, t2.w) + fmaf(b.w, sd.w, td.w));
    reinterpret_cast<float4*>(out)[i] = v;
}

// ---------------------------------------------------------------------------
extern "C" void kernel_launch(void* const* d_in, const int* in_sizes, int n_in,
                              void* d_out, int out_size)
{
    const float* feats = (const float*)d_in[0];
    const int*   nbr1  = (const int*)  d_in[1];
    const int*   nbr2  = (const int*)  d_in[2];
    const float* W1    = (const float*)d_in[3];
    const float* W2    = (const float*)d_in[4];
    const float* Wd    = (const float*)d_in[5];
    const float* g1    = (const float*)d_in[6];
    const float* b1    = (const float*)d_in[7];
    const float* g2    = (const float*)d_in[8];
    const float* b2    = (const float*)d_in[9];
    const float* gd    = (const float*)d_in[10];
    const float* bd    = (const float*)d_in[11];
    float* out = (float*)d_out;

    const int n  = in_sizes[0] / 64;      // 200000
    const int K  = in_sizes[1] / n;       // 27
    const int nb = (n + ROWS - 1) / ROWS; // 3125

    float *h1, *h1t, *h2, *sk, *xt, *wp1, *wp2, *wpd, *p1, *p2, *pd;
    float *sc1, *sh1, *sc2, *sh2, *scd, *shd;
    cudaGetSymbolAddress((void**)&h1,  g_h1);
    cudaGetSymbolAddress((void**)&h1t, g_h1t);
    cudaGetSymbolAddress((void**)&h2,  g_h2);
    cudaGetSymbolAddress((void**)&sk,  g_sk);
    cudaGetSymbolAddress((void**)&xt,  g_xt);
    cudaGetSymbolAddress((void**)&wp1, g_wp1);
    cudaGetSymbolAddress((void**)&wp2, g_wp2);
    cudaGetSymbolAddress((void**)&wpd, g_wpd);
    cudaGetSymbolAddress((void**)&p1,  g_part1);
    cudaGetSymbolAddress((void**)&p2,  g_part2);
    cudaGetSymbolAddress((void**)&pd,  g_partd);
    cudaGetSymbolAddress((void**)&sc1, g_sc1);
    cudaGetSymbolAddress((void**)&sh1, g_sh1);
    cudaGetSymbolAddress((void**)&sc2, g_sc2);
    cudaGetSymbolAddress((void**)&sh2, g_sh2);
    cudaGetSymbolAddress((void**)&scd, g_scd);
    cudaGetSymbolAddress((void**)&shd, g_shd);

    const int smem64  = 2 * ROWS * (64 + 4)  * 4;   // 34816 B
    const int smem128 = 2 * ROWS * (128 + 4) * 4;   // 67584 B
    cudaFuncSetAttribute(conv_mma<64>,
        cudaFuncAttributeMaxDynamicSharedMemorySize, smem64);
    cudaFuncSetAttribute(conv_mma<128>,
        cudaFuncAttributeMaxDynamicSharedMemorySize, smem128);

    // ---- prep (ordered so ncu capture at launch index 3 hits conv1) ----
    const int xt4 = n * (64 / 4);
    cvt_kernel<<<(xt4 + 255) / 256, 256>>>(feats, xt, xt4);          // 0
    {
        int t1 = K * (64 / 8)  * 16 * 32;
        int t2 = K * (128 / 8) * 16 * 32;
        prep_w<<<(t1 + 255) / 256, 256>>>(W1, wp1, K, 64);           // 1
        prep_w<<<(t2 + 255) / 256, 256>>>(W2, wp2, K, 128);          // 2
    }
    // conv1 + BN1 partials                                          // 3
    conv_mma<64><<<nb, NTH, smem64>>>(xt, wp1, nbr1, K, n, h1, p1);
    {
        int td = 1 * (64 / 8) * 16 * 32;
        prep_w<<<(td + 255) / 256, 256>>>(Wd, wpd, 1, 64);           // 4
    }
    // skip (identity gather, K=1) + BNd partials                    // 5
    conv_mma<64><<<nb, NTH, smem64>>>(xt, wpd, nullptr, 1, n, sk, pd);
    bn_finalize<<<128, 256>>>(p1, nb, n, g1, b1, sc1, sh1);
    bn_finalize<<<128, 256>>>(pd, nb, n, gd, bd, scd, shd);
    // h1t = tf32(relu(BN1(h1)))
    const int t4 = n * (COUT / 4);
    bn_relu_cvt<<<(t4 + 255) / 256, 256>>>(h1, sc1, sh1, h1t, t4);
    // conv2 + BN2 partials
    conv_mma<128><<<nb, NTH, smem128>>>(h1t, wp2, nbr2, K, n, h2, p2);
    bn_finalize<<<128, 256>>>(p2, nb, n, g2, b2, sc2, sh2);
    // out = relu(BN2(h2) + BNd(sk))
    final_kernel<<<(t4 + 255) / 256, 256>>>(h2, sk, sc2, sh2,
                                            scd, shd, out, t4);
}

// round 8
// speedup vs baseline: 4.7705x; 2.1045x over previous
#include <cuda_runtime.h>
#include <cuda_fp16.h>
#include <cstdint>

// ---------------------------------------------------------------------------
// SparseResBlock on sm_103a — fp16 mma.sync m16n8k16 (same 10-bit mantissa as
// tf32, half the L1 traffic and half the mma count), 64-row CTA tiles,
// row-paired warps (each B fragment feeds two m16 row tiles).
//   h   = ReLU(BN1(spconv(x, W1, nbr1)))
//   h2  = BN2(spconv(h, W2, nbr2))
//   out = ReLU(h2 + BNd(x @ Wd))
// N=200000, Cin=64, Cout=128, K=27. Accumulation in fp32.
// ---------------------------------------------------------------------------

#define EPS_BN 1e-5f

constexpr int COUT   = 128;
constexpr int ROWS   = 64;        // output rows per CTA
constexpr int NTH    = 256;       // 8 warps: wr in {0,1} x wc in {0..3}
constexpr int MAXN   = 200000;
constexpr int MAXBLK = (MAXN + ROWS - 1) / ROWS;   // 3125

// ---- device-global scratch (no allocation allowed in kernel_launch) ----
__device__ float  g_h1 [(size_t)MAXN * COUT];  // conv1 raw fp32
__device__ __half g_h1t[(size_t)MAXN * COUT];  // relu(BN1(h1)) fp16
__device__ float  g_h2 [(size_t)MAXN * COUT];  // conv2 raw fp32
__device__ float  g_sk [(size_t)MAXN * COUT];  // skip raw fp32
__device__ __half g_xt [(size_t)MAXN * 64];    // feats fp16
__device__ uint2  g_wp1[27 * 4 * 16 * 32];     // W1 frags (k16 chunks)
__device__ uint2  g_wp2[27 * 8 * 16 * 32];     // W2 frags
__device__ uint2  g_wpd[ 1 * 4 * 16 * 32];     // Wd frags
__device__ float g_part1[(size_t)MAXBLK * 256];
__device__ float g_part2[(size_t)MAXBLK * 256];
__device__ float g_partd[(size_t)MAXBLK * 256];
__device__ float g_sc1[COUT], g_sh1[COUT];
__device__ float g_sc2[COUT], g_sh2[COUT];
__device__ float g_scd[COUT], g_shd[COUT];

// ---------------------------------------------------------------------------
__device__ __forceinline__ uint32_t h2u(__half2 h) {
    return *reinterpret_cast<uint32_t*>(&h);
}

__device__ __forceinline__ void cp16(uint32_t dst, const void* src, int sz) {
    // cp.async 16B with runtime src-size (0 => zero-fill)
    asm volatile("cp.async.cg.shared.global [%0], [%1], 16, %2;\n"
                 :: "r"(dst), "l"(src), "r"(sz));
}
__device__ __forceinline__ void cp_commit() {
    asm volatile("cp.async.commit_group;\n" ::: "memory");
}
__device__ __forceinline__ void cp_wait_all() {
    asm volatile("cp.async.wait_group 0;\n" ::: "memory");
}

__device__ __forceinline__ void mma_f16(float acc[4],
                                        uint32_t a0, uint32_t a1,
                                        uint32_t a2, uint32_t a3,
                                        uint32_t b0, uint32_t b1) {
    asm volatile(
        "mma.sync.aligned.m16n8k16.row.col.f32.f16.f16.f32 "
        "{%0,%1,%2,%3}, {%4,%5,%6,%7}, {%8,%9}, {%0,%1,%2,%3};\n"
        : "+f"(acc[0]), "+f"(acc[1]), "+f"(acc[2]), "+f"(acc[3])
        : "r"(a0), "r"(a1), "r"(a2), "r"(a3), "r"(b0), "r"(b1));
}

// ---------------------------------------------------------------------------
// Weight reorder: W[K][CIN][128] -> m16n8k16 .row.col B fragments (fp16).
// uint2 at index ((k*KC + kc)*16 + nt)*32 + lane  (KC = CIN/16):
//   .x = half2{ W[kc*16 + 2tg    ][nt*8 + g], W[kc*16 + 2tg + 1][nt*8 + g] }
//   .y = half2{ W[kc*16 + 2tg + 8][nt*8 + g], W[kc*16 + 2tg + 9][nt*8 + g] }
// (tg = lane&3, g = lane>>2). One warp B-frag load = one coalesced LDG.64.
// ---------------------------------------------------------------------------
__global__ void prep_w(const float* __restrict__ W, uint2* __restrict__ Wp,
                       int K, int CIN)
{
    const int KC    = CIN / 16;
    const int total = K * KC * 16 * 32;
    const int gid   = blockIdx.x * blockDim.x + threadIdx.x;
    if (gid >= total) return;
    const int lane = gid & 31;
    const int tg = lane & 3, g = lane >> 2;
    int t  = gid >> 5;
    const int nt = t & 15;  t >>= 4;
    const int kc = t % KC;
    const int k  = t / KC;
    const int col = nt * 8 + g;
    const size_t b = ((size_t)k * CIN + kc * 16 + 2 * tg) * COUT + col;
    uint2 v;
    v.x = h2u(__floats2half2_rn(W[b],            W[b + COUT]));
    v.y = h2u(__floats2half2_rn(W[b + 8 * COUT], W[b + 9 * COUT]));
    Wp[gid] = v;
}

// elementwise: y = fp16(x), 8 elements per thread
__global__ void cvt_h(const float* __restrict__ x, __half* __restrict__ y,
                      int total8)
{
    const int i = blockIdx.x * blockDim.x + threadIdx.x;
    if (i >= total8) return;
    const float4 f0 = reinterpret_cast<const float4*>(x)[2 * i];
    const float4 f1 = reinterpret_cast<const float4*>(x)[2 * i + 1];
    uint4 o;
    o.x = h2u(__floats2half2_rn(f0.x, f0.y));
    o.y = h2u(__floats2half2_rn(f0.z, f0.w));
    o.z = h2u(__floats2half2_rn(f1.x, f1.y));
    o.w = h2u(__floats2half2_rn(f1.z, f1.w));
    reinterpret_cast<uint4*>(y)[i] = o;
}

// elementwise: y = fp16(relu(x*sc + sh)), per-channel sc/sh (COUT=128)
__global__ void bn_relu_cvt_h(const float* __restrict__ x,
                              const float* __restrict__ sc,
                              const float* __restrict__ sh,
                              __half* __restrict__ y, int total8)
{
    const int i = blockIdx.x * blockDim.x + threadIdx.x;
    if (i >= total8) return;
    const int c = i & 15;                    // 8-channel group
    const float4 f0 = reinterpret_cast<const float4*>(x)[2 * i];
    const float4 f1 = reinterpret_cast<const float4*>(x)[2 * i + 1];
    const float4 s0 = reinterpret_cast<const float4*>(sc)[2 * c];
    const float4 s1 = reinterpret_cast<const float4*>(sc)[2 * c + 1];
    const float4 t0 = reinterpret_cast<const float4*>(sh)[2 * c];
    const float4 t1 = reinterpret_cast<const float4*>(sh)[2 * c + 1];
    uint4 o;
    o.x = h2u(__floats2half2_rn(fmaxf(0.f, fmaf(f0.x, s0.x, t0.x)),
                                fmaxf(0.f, fmaf(f0.y, s0.y, t0.y))));
    o.y = h2u(__floats2half2_rn(fmaxf(0.f, fmaf(f0.z, s0.z, t0.z)),
                                fmaxf(0.f, fmaf(f0.w, s0.w, t0.w))));
    o.z = h2u(__floats2half2_rn(fmaxf(0.f, fmaf(f1.x, s1.x, t1.x)),
                                fmaxf(0.f, fmaf(f1.y, s1.y, t1.y))));
    o.w = h2u(__floats2half2_rn(fmaxf(0.f, fmaf(f1.z, s1.z, t1.z)),
                                fmaxf(0.f, fmaf(f1.w, s1.w, t1.w))));
    reinterpret_cast<uint4*>(y)[i] = o;
}

// ---------------------------------------------------------------------------
// fp16 tensor-core gather-GEMM. CTA: 64 rows x 128 cols. 8 warps:
//   wr = warp&1  -> rows [wr*32, +32)  (two m16 tiles)
//   wc = warp>>1 -> cols [wc*32, +32)  (four n8 tiles)
// Per k16-chunk: 8 scalar LDS.32 (half2 A words, conflict-free: word-stride
// CIN/2+4 = 4 mod 32) + 4 LDG.64 B frags (each feeding TWO mmas) + 8 mma.
// A double-buffered in SMEM via cp.async zero-fill gather.
// Emits per-channel (Sx, Sx^2) BN partials (fp32 accumulators).
// ---------------------------------------------------------------------------
template<int CIN>
__global__ __launch_bounds__(NTH, 3)
void conv_mma(const __half* __restrict__ X,    // [n, CIN] fp16
              const uint2*  __restrict__ Wp,   // fragment-ordered weights
              const int*    __restrict__ nbr,  // [K, n] or nullptr (identity)
              int K, int n,
              float* __restrict__ out,         // [n, COUT] fp32
              float* __restrict__ partial)     // [nb, 256] (Sx | Sxx)
{
    constexpr int V     = CIN / 8;             // 16B units per row
    constexpr int ROW_B = (CIN + 8) * 2;       // padded SMEM row bytes
    constexpr int SW    = CIN / 2 + 4;         // row stride in 4B words
    constexpr int KC    = CIN / 16;            // k16 chunks
    extern __shared__ char smem[];             // [2][ROWS*ROW_B]

    const int tid  = threadIdx.x;
    const int lane = tid & 31, warp = tid >> 5;
    const int wr   = warp & 1,  wc  = warp >> 1;
    const int g    = lane >> 2, tg  = lane & 3;
    const int base = blockIdx.x * ROWS;
    const uint32_t sbase = (uint32_t)__cvta_generic_to_shared(smem);

    float acc[2][4][4];                        // [row tile][n tile][frag]
#pragma unroll
    for (int t = 0; t < 2; ++t)
#pragma unroll
        for (int p = 0; p < 4; ++p)
#pragma unroll
            for (int j = 0; j < 4; ++j) acc[t][p][j] = 0.f;

    // -- async gather of offset k into buffer (k&1); zero-fill missing --
    auto issue = [&](int k) {
        const uint32_t dst0 = sbase + (uint32_t)(k & 1) * (ROWS * ROW_B);
#pragma unroll
        for (int i = 0; i < ROWS * V / NTH; ++i) {
            const int e   = tid + i * NTH;
            const int r   = e / V;
            const int c8  = e - r * V;
            const int row = base + r;
            int idx = -1;
            if (row < n)
                idx = nbr ? __ldg(&nbr[(size_t)k * n + row]) : row;
            const __half* src = X + (size_t)(idx < 0 ? 0 : idx) * CIN + c8 * 8;
            cp16(dst0 + (uint32_t)(r * ROW_B + c8 * 16), src,
                 idx >= 0 ? 16 : 0);
        }
        cp_commit();
    };

    issue(0);
    const int rA = wr * 32 + g;                // row tile 0 (lane view)
    const int rB = rA + 16;                    // row tile 1

    for (int k = 0; k < K; ++k) {
        cp_wait_all();
        __syncthreads();                 // buf k&1 ready
        if (k + 1 < K) issue(k + 1);     // overlap next gather with compute

        const uint32_t* Aw = reinterpret_cast<const uint32_t*>(
            smem + (k & 1) * (ROWS * ROW_B));
#pragma unroll
        for (int kc = 0; kc < KC; ++kc) {
            const int c0 = kc * 8 + tg;
            const uint32_t a0 = Aw[rA * SW + c0];
            const uint32_t a1 = Aw[(rA + 8) * SW + c0];
            const uint32_t a2 = Aw[rA * SW + c0 + 4];
            const uint32_t a3 = Aw[(rA + 8) * SW + c0 + 4];
            const uint32_t b0 = Aw[rB * SW + c0];
            const uint32_t b1 = Aw[(rB + 8) * SW + c0];
            const uint32_t b2 = Aw[rB * SW + c0 + 4];
            const uint32_t b3 = Aw[(rB + 8) * SW + c0 + 4];
            const uint2* Bk = Wp + ((size_t)(k * KC + kc) * 16 + wc * 4) * 32
                            + lane;
#pragma unroll
            for (int p = 0; p < 4; ++p) {
                const uint2 bv = __ldg(&Bk[p * 32]);
                mma_f16(acc[0][p], a0, a1, a2, a3, bv.x, bv.y);  // rows wr*32+
                mma_f16(acc[1][p], b0, b1, b2, b3, bv.x, bv.y);  // rows +16
            }
        }
    }

    // ---- store conv output (fp32) ----
#pragma unroll
    for (int t = 0; t < 2; ++t) {
        const int row = base + wr * 32 + t * 16 + g;
#pragma unroll
        for (int p = 0; p < 4; ++p) {
            const int col = wc * 32 + p * 8 + 2 * tg;
            if (row < n)
                *reinterpret_cast<float2*>(out + (size_t)row * COUT + col) =
                    make_float2(acc[t][p][0], acc[t][p][1]);
            if (row + 8 < n)
                *reinterpret_cast<float2*>(out + (size_t)(row + 8) * COUT + col) =
                    make_float2(acc[t][p][2], acc[t][p][3]);
        }
    }

    // ---- deterministic per-channel partials (Sx, Sx^2) ----
    float s[4][2], q[4][2];
#pragma unroll
    for (int p = 0; p < 4; ++p)
#pragma unroll
        for (int j = 0; j < 2; ++j) {
            s[p][j] = acc[0][p][j] + acc[0][p][j + 2]
                    + acc[1][p][j] + acc[1][p][j + 2];
            q[p][j] = acc[0][p][j]     * acc[0][p][j]
                    + acc[0][p][j + 2] * acc[0][p][j + 2]
                    + acc[1][p][j]     * acc[1][p][j]
                    + acc[1][p][j + 2] * acc[1][p][j + 2];
        }
#pragma unroll
    for (int off = 4; off <= 16; off <<= 1)      // reduce over g (8 lanes)
#pragma unroll
        for (int p = 0; p < 4; ++p)
#pragma unroll
            for (int j = 0; j < 2; ++j) {
                s[p][j] += __shfl_xor_sync(0xffffffffu, s[p][j], off);
                q[p][j] += __shfl_xor_sync(0xffffffffu, q[p][j], off);
            }

    __syncthreads();                              // everyone done with smem
    float* sS = reinterpret_cast<float*>(smem);   // [wr:2][128]
    float* sQ = sS + 256;                         // [wr:2][128]
    if (lane < 4) {                               // g == 0 lanes (tg = lane)
#pragma unroll
        for (int p = 0; p < 4; ++p) {
            const int col = wc * 32 + p * 8 + 2 * tg;
            sS[wr * 128 + col]     = s[p][0];
            sS[wr * 128 + col + 1] = s[p][1];
            sQ[wr * 128 + col]     = q[p][0];
            sQ[wr * 128 + col + 1] = q[p][1];
        }
    }
    __syncthreads();
    if (tid < 128) {
        partial[(size_t)blockIdx.x * 256 + tid] = sS[tid] + sS[128 + tid];
    } else {
        const int c = tid - 128;
        partial[(size_t)blockIdx.x * 256 + 128 + c] = sQ[c] + sQ[128 + c];
    }
}

// ---------------------------------------------------------------------------
// Parallel BN finalize: 128 blocks (one per channel) x 256 threads.
// ---------------------------------------------------------------------------
__global__ void bn_finalize(const float* __restrict__ partial, int nb, int n,
                            const float* __restrict__ gamma,
                            const float* __restrict__ beta,
                            float* __restrict__ scale,
                            float* __restrict__ shift)
{
    const int c = blockIdx.x;
    const int t = threadIdx.x;
    __shared__ double rS[256], rQ[256];
    double S = 0.0, Q = 0.0;
    for (int b = t; b < nb; b += 256) {
        S += (double)partial[(size_t)b * 256 + c];
        Q += (double)partial[(size_t)b * 256 + 128 + c];
    }
    rS[t] = S; rQ[t] = Q;
    __syncthreads();
    for (int off = 128; off > 0; off >>= 1) {
        if (t < off) { rS[t] += rS[t + off]; rQ[t] += rQ[t + off]; }
        __syncthreads();
    }
    if (t == 0) {
        const double mean = rS[0] / n;
        const double var  = rQ[0] / n - mean * mean;
        const float  r    = rsqrtf((float)var + EPS_BN);
        const float  sc   = gamma[c] * r;
        scale[c] = sc;
        shift[c] = beta[c] - (float)mean * sc;
    }
}

// out = relu( h2*sc2 + sh2 + sk*scd + shd )
__global__ void final_kernel(const float* __restrict__ h2,
                             const float* __restrict__ sk,
                             const float* __restrict__ sc2,
                             const float* __restrict__ sh2,
                             const float* __restrict__ scd,
                             const float* __restrict__ shd,
                             float* __restrict__ out, int total4)
{
    const int i = blockIdx.x * blockDim.x + threadIdx.x;
    if (i >= total4) return;
    const int c4 = i & 31;
    const float4 a  = reinterpret_cast<const float4*>(h2)[i];
    const float4 b  = reinterpret_cast<const float4*>(sk)[i];
    const float4 s2 = reinterpret_cast<const float4*>(sc2)[c4];
    const float4 t2 = reinterpret_cast<const float4*>(sh2)[c4];
    const float4 sd = reinterpret_cast<const float4*>(scd)[c4];
    const float4 td = reinterpret_cast<const float4*>(shd)[c4];
    float4 v;
    v.x = fmaxf(0.f, fmaf(a.x, s2.x, t2.x) + fmaf(b.x, sd.x, td.x));
    v.y = fmaxf(0.f, fmaf(a.y, s2.y, t2.y) + fmaf(b.y, sd.y, td.y));
    v.z = fmaxf(0.f, fmaf(a.z, s2.z, t2.z) + fmaf(b.z, sd.z, td.z));
    v.w = fmaxf(0.f, fmaf(a.w, s2.w, t2.w) + fmaf(b.w, sd.w, td.w));
    reinterpret_cast<float4*>(out)[i] = v;
}

// ---------------------------------------------------------------------------
extern "C" void kernel_launch(void* const* d_in, const int* in_sizes, int n_in,
                              void* d_out, int out_size)
{
    const float* feats = (const float*)d_in[0];
    const int*   nbr1  = (const int*)  d_in[1];
    const int*   nbr2  = (const int*)  d_in[2];
    const float* W1    = (const float*)d_in[3];
    const float* W2    = (const float*)d_in[4];
    const float* Wd    = (const float*)d_in[5];
    const float* g1    = (const float*)d_in[6];
    const float* b1    = (const float*)d_in[7];
    const float* g2    = (const float*)d_in[8];
    const float* b2    = (const float*)d_in[9];
    const float* gd    = (const float*)d_in[10];
    const float* bd    = (const float*)d_in[11];
    float* out = (float*)d_out;

    const int n  = in_sizes[0] / 64;      // 200000
    const int K  = in_sizes[1] / n;       // 27
    const int nb = (n + ROWS - 1) / ROWS; // 3125

    float *h1, *h2, *sk, *p1, *p2, *pd;
    __half *h1t, *xt;
    uint2 *wp1, *wp2, *wpd;
    float *sc1, *sh1, *sc2, *sh2, *scd, *shd;
    cudaGetSymbolAddress((void**)&h1,  g_h1);
    cudaGetSymbolAddress((void**)&h1t, g_h1t);
    cudaGetSymbolAddress((void**)&h2,  g_h2);
    cudaGetSymbolAddress((void**)&sk,  g_sk);
    cudaGetSymbolAddress((void**)&xt,  g_xt);
    cudaGetSymbolAddress((void**)&wp1, g_wp1);
    cudaGetSymbolAddress((void**)&wp2, g_wp2);
    cudaGetSymbolAddress((void**)&wpd, g_wpd);
    cudaGetSymbolAddress((void**)&p1,  g_part1);
    cudaGetSymbolAddress((void**)&p2,  g_part2);
    cudaGetSymbolAddress((void**)&pd,  g_partd);
    cudaGetSymbolAddress((void**)&sc1, g_sc1);
    cudaGetSymbolAddress((void**)&sh1, g_sh1);
    cudaGetSymbolAddress((void**)&sc2, g_sc2);
    cudaGetSymbolAddress((void**)&sh2, g_sh2);
    cudaGetSymbolAddress((void**)&scd, g_scd);
    cudaGetSymbolAddress((void**)&shd, g_shd);

    const int smem64  = 2 * ROWS * (64 + 8)  * 2;   // 18432 B
    const int smem128 = 2 * ROWS * (128 + 8) * 2;   // 34816 B

    // ---- prep (ordered so ncu capture at launch index 3 hits conv1) ----
    const int xt8 = n * (64 / 8);
    cvt_h<<<(xt8 + 255) / 256, 256>>>(feats, xt, xt8);               // 0
    {
        int t1 = K * (64 / 16)  * 16 * 32;
        int t2 = K * (128 / 16) * 16 * 32;
        prep_w<<<(t1 + 255) / 256, 256>>>(W1, wp1, K, 64);           // 1
        prep_w<<<(t2 + 255) / 256, 256>>>(W2, wp2, K, 128);          // 2
    }
    // conv1 + BN1 partials                                          // 3
    conv_mma<64><<<nb, NTH, smem64>>>(xt, wp1, nbr1, K, n, h1, p1);
    {
        int td = 1 * (64 / 16) * 16 * 32;
        prep_w<<<(td + 255) / 256, 256>>>(Wd, wpd, 1, 64);           // 4
    }
    // skip (identity gather, K=1) + BNd partials                    // 5
    conv_mma<64><<<nb, NTH, smem64>>>(xt, wpd, nullptr, 1, n, sk, pd);
    bn_finalize<<<128, 256>>>(p1, nb, n, g1, b1, sc1, sh1);
    bn_finalize<<<128, 256>>>(pd, nb, n, gd, bd, scd, shd);
    // h1t = fp16(relu(BN1(h1)))
    const int t8 = n * (COUT / 8);
    bn_relu_cvt_h<<<(t8 + 255) / 256, 256>>>(h1, sc1, sh1, h1t, t8);
    // conv2 + BN2 partials
    conv_mma<128><<<nb, NTH, smem128>>>(h1t, wp2, nbr2, K, n, h2, p2);
    bn_finalize<<<128, 256>>>(p2, nb, n, g2, b2, sc2, sh2);
    // out = relu(BN2(h2) + BNd(sk))
    const int t4 = n * (COUT / 4);
    final_kernel<<<(t4 + 255) / 256, 256>>>(h2, sk, sc2, sh2,
                                            scd, shd, out, t4);
}

// round 10
// speedup vs baseline: 5.1663x; 1.0830x over previous
#include <cuda_runtime.h>
#include <cuda_fp16.h>
#include <cstdint>

// ---------------------------------------------------------------------------
// SparseResBlock on sm_103a — fp16 mma.sync m16n8k16, 128-row CTA tiles,
// RT=4 row tiles x NT=4 n-tiles per warp (B fragment reuse x4, A reuse x4):
// cuts per-mma L1 bytes 281 -> 218 (the measured bottleneck).
//   h   = ReLU(BN1(spconv(x, W1, nbr1)))
//   h2  = BN2(spconv(h, W2, nbr2))
//   out = ReLU(h2 + BNd(x @ Wd))
// N=200000, Cin=64, Cout=128, K=27. Accumulation in fp32.
// ---------------------------------------------------------------------------

#define EPS_BN 1e-5f

constexpr int COUT   = 128;
constexpr int ROWS   = 128;       // output rows per CTA
constexpr int NTH    = 256;       // 8 warps: wr in {0,1} x wc in {0..3}
constexpr int MAXN   = 200000;
constexpr int MAXBLK = (MAXN + ROWS - 1) / ROWS;   // 1563

// ---- device-global scratch (no allocation allowed in kernel_launch) ----
__device__ float  g_h1 [(size_t)MAXN * COUT];  // conv1 raw fp32
__device__ __half g_h1t[(size_t)MAXN * COUT];  // relu(BN1(h1)) fp16
__device__ float  g_h2 [(size_t)MAXN * COUT];  // conv2 raw fp32
__device__ float  g_sk [(size_t)MAXN * COUT];  // skip raw fp32
__device__ __half g_xt [(size_t)MAXN * 64];    // feats fp16
__device__ uint2  g_wp1[27 * 4 * 16 * 32];     // W1 frags (k16 chunks)
__device__ uint2  g_wp2[27 * 8 * 16 * 32];     // W2 frags
__device__ uint2  g_wpd[ 1 * 4 * 16 * 32];     // Wd frags
__device__ float g_part1[(size_t)MAXBLK * 256];
__device__ float g_part2[(size_t)MAXBLK * 256];
__device__ float g_partd[(size_t)MAXBLK * 256];
__device__ float g_sc1[COUT], g_sh1[COUT];
__device__ float g_sc2[COUT], g_sh2[COUT];
__device__ float g_scd[COUT], g_shd[COUT];

// ---------------------------------------------------------------------------
__device__ __forceinline__ uint32_t h2u(__half2 h) {
    return *reinterpret_cast<uint32_t*>(&h);
}

__device__ __forceinline__ void cp16(uint32_t dst, const void* src, int sz) {
    // cp.async 16B with runtime src-size (0 => zero-fill)
    asm volatile("cp.async.cg.shared.global [%0], [%1], 16, %2;\n"
                 :: "r"(dst), "l"(src), "r"(sz));
}
__device__ __forceinline__ void cp_commit() {
    asm volatile("cp.async.commit_group;\n" ::: "memory");
}
__device__ __forceinline__ void cp_wait_all() {
    asm volatile("cp.async.wait_group 0;\n" ::: "memory");
}

__device__ __forceinline__ void mma_f16(float acc[4],
                                        uint32_t a0, uint32_t a1,
                                        uint32_t a2, uint32_t a3,
                                        uint32_t b0, uint32_t b1) {
    asm volatile(
        "mma.sync.aligned.m16n8k16.row.col.f32.f16.f16.f32 "
        "{%0,%1,%2,%3}, {%4,%5,%6,%7}, {%8,%9}, {%0,%1,%2,%3};\n"
        : "+f"(acc[0]), "+f"(acc[1]), "+f"(acc[2]), "+f"(acc[3])
        : "r"(a0), "r"(a1), "r"(a2), "r"(a3), "r"(b0), "r"(b1));
}

// ---------------------------------------------------------------------------
// Weight reorder: W[K][CIN][128] -> m16n8k16 .row.col B fragments (fp16).
// uint2 at index ((k*KC + kc)*16 + nt)*32 + lane  (KC = CIN/16):
//   .x = half2{ W[kc*16 + 2tg    ][nt*8 + g], W[kc*16 + 2tg + 1][nt*8 + g] }
//   .y = half2{ W[kc*16 + 2tg + 8][nt*8 + g], W[kc*16 + 2tg + 9][nt*8 + g] }
// (tg = lane&3, g = lane>>2). One warp B-frag load = one coalesced LDG.64.
// ---------------------------------------------------------------------------
__global__ void prep_w(const float* __restrict__ W, uint2* __restrict__ Wp,
                       int K, int CIN)
{
    const int KC    = CIN / 16;
    const int total = K * KC * 16 * 32;
    const int gid   = blockIdx.x * blockDim.x + threadIdx.x;
    if (gid >= total) return;
    const int lane = gid & 31;
    const int tg = lane & 3, g = lane >> 2;
    int t  = gid >> 5;
    const int nt = t & 15;  t >>= 4;
    const int kc = t % KC;
    const int k  = t / KC;
    const int col = nt * 8 + g;
    const size_t b = ((size_t)k * CIN + kc * 16 + 2 * tg) * COUT + col;
    uint2 v;
    v.x = h2u(__floats2half2_rn(W[b],            W[b + COUT]));
    v.y = h2u(__floats2half2_rn(W[b + 8 * COUT], W[b + 9 * COUT]));
    Wp[gid] = v;
}

// elementwise: y = fp16(x), 8 elements per thread
__global__ void cvt_h(const float* __restrict__ x, __half* __restrict__ y,
                      int total8)
{
    const int i = blockIdx.x * blockDim.x + threadIdx.x;
    if (i >= total8) return;
    const float4 f0 = reinterpret_cast<const float4*>(x)[2 * i];
    const float4 f1 = reinterpret_cast<const float4*>(x)[2 * i + 1];
    uint4 o;
    o.x = h2u(__floats2half2_rn(f0.x, f0.y));
    o.y = h2u(__floats2half2_rn(f0.z, f0.w));
    o.z = h2u(__floats2half2_rn(f1.x, f1.y));
    o.w = h2u(__floats2half2_rn(f1.z, f1.w));
    reinterpret_cast<uint4*>(y)[i] = o;
}

// elementwise: y = fp16(relu(x*sc + sh)), per-channel sc/sh (COUT=128)
__global__ void bn_relu_cvt_h(const float* __restrict__ x,
                              const float* __restrict__ sc,
                              const float* __restrict__ sh,
                              __half* __restrict__ y, int total8)
{
    const int i = blockIdx.x * blockDim.x + threadIdx.x;
    if (i >= total8) return;
    const int c = i & 15;                    // 8-channel group
    const float4 f0 = reinterpret_cast<const float4*>(x)[2 * i];
    const float4 f1 = reinterpret_cast<const float4*>(x)[2 * i + 1];
    const float4 s0 = reinterpret_cast<const float4*>(sc)[2 * c];
    const float4 s1 = reinterpret_cast<const float4*>(sc)[2 * c + 1];
    const float4 t0 = reinterpret_cast<const float4*>(sh)[2 * c];
    const float4 t1 = reinterpret_cast<const float4*>(sh)[2 * c + 1];
    uint4 o;
    o.x = h2u(__floats2half2_rn(fmaxf(0.f, fmaf(f0.x, s0.x, t0.x)),
                                fmaxf(0.f, fmaf(f0.y, s0.y, t0.y))));
    o.y = h2u(__floats2half2_rn(fmaxf(0.f, fmaf(f0.z, s0.z, t0.z)),
                                fmaxf(0.f, fmaf(f0.w, s0.w, t0.w))));
    o.z = h2u(__floats2half2_rn(fmaxf(0.f, fmaf(f1.x, s1.x, t1.x)),
                                fmaxf(0.f, fmaf(f1.y, s1.y, t1.y))));
    o.w = h2u(__floats2half2_rn(fmaxf(0.f, fmaf(f1.z, s1.z, t1.z)),
                                fmaxf(0.f, fmaf(f1.w, s1.w, t1.w))));
    reinterpret_cast<uint4*>(y)[i] = o;
}

// ---------------------------------------------------------------------------
// fp16 tensor-core gather-GEMM. CTA: 128 rows x 128 cols. 8 warps:
//   wr = warp&1  -> rows [wr*64, +64)  (FOUR m16 tiles, t = 0..3)
//   wc = warp>>1 -> cols [wc*32, +32)  (four n8 tiles, p = 0..3)
// Per k16-chunk: 16 LDS.32 (A words, conflict-free: stride = 4 mod 32)
// + 4 LDG.64 B frags (each feeding FOUR mmas) + 16 mma.
// A double-buffered in SMEM via cp.async zero-fill gather.
// Emits per-channel (Sx, Sx^2) BN partials (fp32 accumulators).
// ---------------------------------------------------------------------------
template<int CIN>
__global__ __launch_bounds__(NTH, 2)
void conv_mma(const __half* __restrict__ X,    // [n, CIN] fp16
              const uint2*  __restrict__ Wp,   // fragment-ordered weights
              const int*    __restrict__ nbr,  // [K, n] or nullptr (identity)
              int K, int n,
              float* __restrict__ out,         // [n, COUT] fp32
              float* __restrict__ partial)     // [nb, 256] (Sx | Sxx)
{
    constexpr int V     = CIN / 8;             // 16B units per row
    constexpr int ROW_B = (CIN + 8) * 2;       // padded SMEM row bytes
    constexpr int SW    = CIN / 2 + 4;         // row stride in 4B words
    constexpr int KC    = CIN / 16;            // k16 chunks
    extern __shared__ char smem[];             // [2][ROWS*ROW_B]

    const int tid  = threadIdx.x;
    const int lane = tid & 31, warp = tid >> 5;
    const int wr   = warp & 1,  wc  = warp >> 1;
    const int g    = lane >> 2, tg  = lane & 3;
    const int base = blockIdx.x * ROWS;
    const uint32_t sbase = (uint32_t)__cvta_generic_to_shared(smem);

    float acc[4][4][4];                        // [row tile][n tile][frag]
#pragma unroll
    for (int t = 0; t < 4; ++t)
#pragma unroll
        for (int p = 0; p < 4; ++p)
#pragma unroll
            for (int j = 0; j < 4; ++j) acc[t][p][j] = 0.f;

    // -- async gather of offset k into buffer (k&1); zero-fill missing --
    auto issue = [&](int k) {
        const uint32_t dst0 = sbase + (uint32_t)(k & 1) * (ROWS * ROW_B);
#pragma unroll
        for (int i = 0; i < ROWS * V / NTH; ++i) {
            const int e   = tid + i * NTH;
            const int r   = e / V;
            const int c8  = e - r * V;
            const int row = base + r;
            int idx = -1;
            if (row < n)
                idx = nbr ? __ldg(&nbr[(size_t)k * n + row]) : row;
            const __half* src = X + (size_t)(idx < 0 ? 0 : idx) * CIN + c8 * 8;
            cp16(dst0 + (uint32_t)(r * ROW_B + c8 * 16), src,
                 idx >= 0 ? 16 : 0);
        }
        cp_commit();
    };

    issue(0);
    const int r0 = wr * 64 + g;                // row tile t base: r0 + t*16

    for (int k = 0; k < K; ++k) {
        cp_wait_all();
        __syncthreads();                 // buf k&1 ready
        if (k + 1 < K) issue(k + 1);     // overlap next gather with compute

        const uint32_t* Aw = reinterpret_cast<const uint32_t*>(
            smem + (k & 1) * (ROWS * ROW_B));
#pragma unroll
        for (int kc = 0; kc < KC; ++kc) {
            const int c0 = kc * 8 + tg;
            uint32_t a[4][4];
#pragma unroll
            for (int t = 0; t < 4; ++t) {
                const int r = r0 + t * 16;
                a[t][0] = Aw[r * SW + c0];
                a[t][1] = Aw[(r + 8) * SW + c0];
                a[t][2] = Aw[r * SW + c0 + 4];
                a[t][3] = Aw[(r + 8) * SW + c0 + 4];
            }
            const uint2* Bk = Wp + ((size_t)(k * KC + kc) * 16 + wc * 4) * 32
                            + lane;
#pragma unroll
            for (int p = 0; p < 4; ++p) {
                const uint2 bv = __ldg(&Bk[p * 32]);
#pragma unroll
                for (int t = 0; t < 4; ++t)
                    mma_f16(acc[t][p], a[t][0], a[t][1], a[t][2], a[t][3],
                            bv.x, bv.y);
            }
        }
    }

    // ---- store conv output (fp32) ----
#pragma unroll
    for (int t = 0; t < 4; ++t) {
        const int row = base + wr * 64 + t * 16 + g;
#pragma unroll
        for (int p = 0; p < 4; ++p) {
            const int col = wc * 32 + p * 8 + 2 * tg;
            if (row < n)
                *reinterpret_cast<float2*>(out + (size_t)row * COUT + col) =
                    make_float2(acc[t][p][0], acc[t][p][1]);
            if (row + 8 < n)
                *reinterpret_cast<float2*>(out + (size_t)(row + 8) * COUT + col) =
                    make_float2(acc[t][p][2], acc[t][p][3]);
        }
    }

    // ---- deterministic per-channel partials (Sx, Sx^2) ----
    float s[4][2], q[4][2];
#pragma unroll
    for (int p = 0; p < 4; ++p)
#pragma unroll
        for (int j = 0; j < 2; ++j) {
            float ss = 0.f, qq = 0.f;
#pragma unroll
            for (int t = 0; t < 4; ++t) {
                ss += acc[t][p][j] + acc[t][p][j + 2];
                qq += acc[t][p][j]     * acc[t][p][j]
                    + acc[t][p][j + 2] * acc[t][p][j + 2];
            }
            s[p][j] = ss; q[p][j] = qq;
        }
#pragma unroll
    for (int off = 4; off <= 16; off <<= 1)      // reduce over g (8 lanes)
#pragma unroll
        for (int p = 0; p < 4; ++p)
#pragma unroll
            for (int j = 0; j < 2; ++j) {
                s[p][j] += __shfl_xor_sync(0xffffffffu, s[p][j], off);
                q[p][j] += __shfl_xor_sync(0xffffffffu, q[p][j], off);
            }

    __syncthreads();                              // everyone done with smem
    float* sS = reinterpret_cast<float*>(smem);   // [wr:2][128]
    float* sQ = sS + 256;                         // [wr:2][128]
    if (lane < 4) {                               // g == 0 lanes (tg = lane)
#pragma unroll
        for (int p = 0; p < 4; ++p) {
            const int col = wc * 32 + p * 8 + 2 * tg;
            sS[wr * 128 + col]     = s[p][0];
            sS[wr * 128 + col + 1] = s[p][1];
            sQ[wr * 128 + col]     = q[p][0];
            sQ[wr * 128 + col + 1] = q[p][1];
        }
    }
    __syncthreads();
    if (tid < 128) {
        partial[(size_t)blockIdx.x * 256 + tid] = sS[tid] + sS[128 + tid];
    } else {
        const int c = tid - 128;
        partial[(size_t)blockIdx.x * 256 + 128 + c] = sQ[c] + sQ[128 + c];
    }
}

// ---------------------------------------------------------------------------
// Parallel BN finalize: 128 blocks (one per channel) x 256 threads.
// ---------------------------------------------------------------------------
__global__ void bn_finalize(const float* __restrict__ partial, int nb, int n,
                            const float* __restrict__ gamma,
                            const float* __restrict__ beta,
                            float* __restrict__ scale,
                            float* __restrict__ shift)
{
    const int c = blockIdx.x;
    const int t = threadIdx.x;
    __shared__ double rS[256], rQ[256];
    double S = 0.0, Q = 0.0;
    for (int b = t; b < nb; b += 256) {
        S += (double)partial[(size_t)b * 256 + c];
        Q += (double)partial[(size_t)b * 256 + 128 + c];
    }
    rS[t] = S; rQ[t] = Q;
    __syncthreads();
    for (int off = 128; off > 0; off >>= 1) {
        if (t < off) { rS[t] += rS[t + off]; rQ[t] += rQ[t + off]; }
        __syncthreads();
    }
    if (t == 0) {
        const double mean = rS[0] / n;
        const double var  = rQ[0] / n - mean * mean;
        const float  r    = rsqrtf((float)var + EPS_BN);
        const float  sc   = gamma[c] * r;
        scale[c] = sc;
        shift[c] = beta[c] - (float)mean * sc;
    }
}

// out = relu( h2*sc2 + sh2 + sk*scd + shd )
__global__ void final_kernel(const float* __restrict__ h2,
                             const float* __restrict__ sk,
                             const float* __restrict__ sc2,
                             const float* __restrict__ sh2,
                             const float* __restrict__ scd,
                             const float* __restrict__ shd,
                             float* __restrict__ out, int total4)
{
    const int i = blockIdx.x * blockDim.x + threadIdx.x;
    if (i >= total4) return;
    const int c4 = i & 31;
    const float4 a  = reinterpret_cast<const float4*>(h2)[i];
    const float4 b  = reinterpret_cast<const float4*>(sk)[i];
    const float4 s2 = reinterpret_cast<const float4*>(sc2)[c4];
    const float4 t2 = reinterpret_cast<const float4*>(sh2)[c4];
    const float4 sd = reinterpret_cast<const float4*>(scd)[c4];
    const float4 td = reinterpret_cast<const float4*>(shd)[c4];
    float4 v;
    v.x = fmaxf(0.f, fmaf(a.x, s2.x, t2.x) + fmaf(b.x, sd.x, td.x));
    v.y = fmaxf(0.f, fmaf(a.y, s2.y, t2.y) + fmaf(b.y, sd.y, td.y));
    v.z = fmaxf(0.f, fmaf(a.z, s2.z, t2.z) + fmaf(b.z, sd.z, td.z));
    v.w = fmaxf(0.f, fmaf(a.w, s2.w, t2.w) + fmaf(b.w, sd.w, td.w));
    reinterpret_cast<float4*>(out)[i] = v;
}

// ---------------------------------------------------------------------------
extern "C" void kernel_launch(void* const* d_in, const int* in_sizes, int n_in,
                              void* d_out, int out_size)
{
    const float* feats = (const float*)d_in[0];
    const int*   nbr1  = (const int*)  d_in[1];
    const int*   nbr2  = (const int*)  d_in[2];
    const float* W1    = (const float*)d_in[3];
    const float* W2    = (const float*)d_in[4];
    const float* Wd    = (const float*)d_in[5];
    const float* g1    = (const float*)d_in[6];
    const float* b1    = (const float*)d_in[7];
    const float* g2    = (const float*)d_in[8];
    const float* b2    = (const float*)d_in[9];
    const float* gd    = (const float*)d_in[10];
    const float* bd    = (const float*)d_in[11];
    float* out = (float*)d_out;

    const int n  = in_sizes[0] / 64;      // 200000
    const int K  = in_sizes[1] / n;       // 27
    const int nb = (n + ROWS - 1) / ROWS; // 1563

    float *h1, *h2, *sk, *p1, *p2, *pd;
    __half *h1t, *xt;
    uint2 *wp1, *wp2, *wpd;
    float *sc1, *sh1, *sc2, *sh2, *scd, *shd;
    cudaGetSymbolAddress((void**)&h1,  g_h1);
    cudaGetSymbolAddress((void**)&h1t, g_h1t);
    cudaGetSymbolAddress((void**)&h2,  g_h2);
    cudaGetSymbolAddress((void**)&sk,  g_sk);
    cudaGetSymbolAddress((void**)&xt,  g_xt);
    cudaGetSymbolAddress((void**)&wp1, g_wp1);
    cudaGetSymbolAddress((void**)&wp2, g_wp2);
    cudaGetSymbolAddress((void**)&wpd, g_wpd);
    cudaGetSymbolAddress((void**)&p1,  g_part1);
    cudaGetSymbolAddress((void**)&p2,  g_part2);
    cudaGetSymbolAddress((void**)&pd,  g_partd);
    cudaGetSymbolAddress((void**)&sc1, g_sc1);
    cudaGetSymbolAddress((void**)&sh1, g_sh1);
    cudaGetSymbolAddress((void**)&sc2, g_sc2);
    cudaGetSymbolAddress((void**)&sh2, g_sh2);
    cudaGetSymbolAddress((void**)&scd, g_scd);
    cudaGetSymbolAddress((void**)&shd, g_shd);

    const int smem64  = 2 * ROWS * (64 + 8)  * 2;   // 36864 B
    const int smem128 = 2 * ROWS * (128 + 8) * 2;   // 69632 B
    cudaFuncSetAttribute(conv_mma<64>,
        cudaFuncAttributeMaxDynamicSharedMemorySize, smem64);
    cudaFuncSetAttribute(conv_mma<128>,
        cudaFuncAttributeMaxDynamicSharedMemorySize, smem128);

    // ---- prep (ordered so ncu capture at launch index 3 hits conv1) ----
    const int xt8 = n * (64 / 8);
    cvt_h<<<(xt8 + 255) / 256, 256>>>(feats, xt, xt8);               // 0
    {
        int t1 = K * (64 / 16)  * 16 * 32;
        int t2 = K * (128 / 16) * 16 * 32;
        prep_w<<<(t1 + 255) / 256, 256>>>(W1, wp1, K, 64);           // 1
        prep_w<<<(t2 + 255) / 256, 256>>>(W2, wp2, K, 128);          // 2
    }
    // conv1 + BN1 partials                                          // 3
    conv_mma<64><<<nb, NTH, smem64>>>(xt, wp1, nbr1, K, n, h1, p1);
    {
        int td = 1 * (64 / 16) * 16 * 32;
        prep_w<<<(td + 255) / 256, 256>>>(Wd, wpd, 1, 64);           // 4
    }
    // skip (identity gather, K=1) + BNd partials
    conv_mma<64><<<nb, NTH, smem64>>>(xt, wpd, nullptr, 1, n, sk, pd);
    bn_finalize<<<128, 256>>>(p1, nb, n, g1, b1, sc1, sh1);
    bn_finalize<<<128, 256>>>(pd, nb, n, gd, bd, scd, shd);
    // h1t = fp16(relu(BN1(h1)))
    const int t8 = n * (COUT / 8);
    bn_relu_cvt_h<<<(t8 + 255) / 256, 256>>>(h1, sc1, sh1, h1t, t8);
    // conv2 + BN2 partials
    conv_mma<128><<<nb, NTH, smem128>>>(h1t, wp2, nbr2, K, n, h2, p2);
    bn_finalize<<<128, 256>>>(p2, nb, n, g2, b2, sc2, sh2);
    // out = relu(BN2(h2) + BNd(sk))
    const int t4 = n * (COUT / 4);
    final_kernel<<<(t4 + 255) / 256, 256>>>(h2, sk, sc2, sh2,
                                            scd, shd, out, t4);
}